// round 1
// baseline (speedup 1.0000x reference)
#include <cuda_runtime.h>
#include <math.h>

#define BB 8
#define SS 2048
#define EE 256
#define LL 4
#define FF 1024
#define NQ 8
#define NC 10
#define NH 32
#define ROWS (BB*SS)   // 16384

// ---------------- scratch (static device arrays; no allocation) ----------------
__device__ float d_x[ROWS*EE];   // activations  (16 MB)
__device__ float d_q[ROWS*EE];   // quantum-attention q (16 MB)
__device__ float d_a[ROWS*EE];   // attention out / ffn out (16 MB)
__device__ float d_h[(size_t)ROWS*FF]; // ffn hidden (64 MB)

// ---------------- 1. embedding + positional encoding ----------------
__global__ void embed_kernel(const int* __restrict__ tok, const float* __restrict__ emb) {
    int gidx = blockIdx.x * blockDim.x + threadIdx.x;   // ROWS*EE threads
    int row = gidx >> 8;
    int e = gidx & 255;
    int s = row & (SS - 1);
    // pe: freq = exp(-(e&~1) * ln(10000)/256); even->sin, odd->cos
    double freq = exp((double)(e & ~1) * (-9.210340371976184 / 256.0));
    double ang = (double)s * freq;
    float pe = (e & 1) ? (float)cos(ang) : (float)sin(ang);
    d_x[gidx] = emb[(size_t)tok[row] * EE + e] + pe;
}

// ---------------- 2. quantum attention q-map ----------------
// per head (dk=8): c_j = cos(x_j + phi_j); q_0 = prod_{j>=1} c_j; q_i = prod_{j<=i} c_j (i>=1)
__global__ void qmap_kernel(const float* __restrict__ phi) {
    int g = blockIdx.x * blockDim.x + threadIdx.x;      // ROWS*NH threads
    int base = g * NQ;                                  // == row*256 + head*8
    float4 a0 = *(const float4*)(d_x + base);
    float4 a1 = *(const float4*)(d_x + base + 4);
    float c[8];
    c[0] = cosf(a0.x + phi[0]); c[1] = cosf(a0.y + phi[1]);
    c[2] = cosf(a0.z + phi[2]); c[3] = cosf(a0.w + phi[3]);
    c[4] = cosf(a1.x + phi[4]); c[5] = cosf(a1.y + phi[5]);
    c[6] = cosf(a1.z + phi[6]); c[7] = cosf(a1.w + phi[7]);
    float out[8];
    float t = c[1];
    #pragma unroll
    for (int j = 2; j < 8; j++) t *= c[j];
    out[0] = t;                                         // wire 0: prod_{j>=1}
    float pref = c[0];
    #pragma unroll
    for (int i = 1; i < 8; i++) { pref *= c[i]; out[i] = pref; }
    float4 o0 = make_float4(out[0], out[1], out[2], out[3]);
    float4 o1 = make_float4(out[4], out[5], out[6], out[7]);
    *(float4*)(d_q + base) = o0;
    *(float4*)(d_q + base + 4) = o1;
}

// ---------------- 3. flash attention (Q = K = V = q) ----------------
// Block: 256 threads = 8 warps; warp handles 4 rows; lane (r=lane>>3, g=lane&7)
// owns float4 slice e = i*32 + g*4 (i=0..7) -> bank-conflict-free smem access.
#define KT 32
__global__ __launch_bounds__(256) void attn_kernel() {
    __shared__ float Ks[KT][EE];
    int b = blockIdx.y;
    int warp = threadIdx.x >> 5, lane = threadIdx.x & 31;
    int r = lane >> 3, g = lane & 7;
    int row = blockIdx.x * 32 + warp * 4 + r;
    const float* qb = d_q + (size_t)b * SS * EE;
    const float scale = 0.35355339059327373f;           // 1/sqrt(8)

    float4 qv[8], ov[8];
    const float4* qrow = (const float4*)(qb + (size_t)row * EE);
    #pragma unroll
    for (int i = 0; i < 8; i++) {
        float4 v = qrow[i * 8 + g];
        v.x *= scale; v.y *= scale; v.z *= scale; v.w *= scale;
        qv[i] = v;
        ov[i] = make_float4(0.f, 0.f, 0.f, 0.f);
    }
    float m = -3.4e38f, l = 0.f;

    for (int t = 0; t < SS / KT; t++) {
        __syncthreads();
        const float4* src = (const float4*)(qb + (size_t)t * KT * EE);
        float4* dst = (float4*)Ks;
        #pragma unroll
        for (int p = 0; p < (KT * EE / 4) / 256; p++)
            dst[p * 256 + threadIdx.x] = src[p * 256 + threadIdx.x];
        __syncthreads();

        for (int j = 0; j < KT; j++) {
            const float4* kr = (const float4*)Ks[j];
            float s = 0.f;
            #pragma unroll
            for (int i = 0; i < 8; i++) {
                float4 kv = kr[i * 8 + g];
                s += qv[i].x * kv.x + qv[i].y * kv.y + qv[i].z * kv.z + qv[i].w * kv.w;
            }
            // reduce over g (low 3 lane bits); rows stay independent
            s += __shfl_xor_sync(0xffffffffu, s, 1);
            s += __shfl_xor_sync(0xffffffffu, s, 2);
            s += __shfl_xor_sync(0xffffffffu, s, 4);
            if (s > m) {
                float corr = __expf(m - s);
                l *= corr;
                #pragma unroll
                for (int i = 0; i < 8; i++) {
                    ov[i].x *= corr; ov[i].y *= corr; ov[i].z *= corr; ov[i].w *= corr;
                }
                m = s;
            }
            float p = __expf(s - m);
            l += p;
            #pragma unroll
            for (int i = 0; i < 8; i++) {
                float4 kv = kr[i * 8 + g];
                ov[i].x += p * kv.x; ov[i].y += p * kv.y;
                ov[i].z += p * kv.z; ov[i].w += p * kv.w;
            }
        }
    }
    float inv = 1.f / l;
    float4* arow = (float4*)(d_a + ((size_t)b * SS + row) * EE);
    #pragma unroll
    for (int i = 0; i < 8; i++) {
        float4 v = ov[i];
        v.x *= inv; v.y *= inv; v.z *= inv; v.w *= inv;
        arow[i * 8 + g] = v;
    }
}

// ---------------- 4. x = LayerNorm(x + a) ----------------
// warp per row (E=256 -> 8 elems/lane)
__global__ void addln_kernel(const float* __restrict__ gam, const float* __restrict__ bet) {
    int warp = threadIdx.x >> 5, lane = threadIdx.x & 31;
    int row = blockIdx.x * 8 + warp;
    float* xr = d_x + (size_t)row * EE;
    const float* fr = d_a + (size_t)row * EE;
    float v[8];
    float sum = 0.f, sq = 0.f;
    #pragma unroll
    for (int i = 0; i < 8; i++) {
        int e = lane + 32 * i;
        v[i] = xr[e] + fr[e];
        sum += v[i];
        sq += v[i] * v[i];
    }
    #pragma unroll
    for (int mask = 16; mask >= 1; mask >>= 1) {
        sum += __shfl_xor_sync(0xffffffffu, sum, mask);
        sq  += __shfl_xor_sync(0xffffffffu, sq, mask);
    }
    float mean = sum * (1.f / EE);
    float var = sq * (1.f / EE) - mean * mean;
    float inv = rsqrtf(var + 1e-5f);
    #pragma unroll
    for (int i = 0; i < 8; i++) {
        int e = lane + 32 * i;
        xr[e] = (v[i] - mean) * inv * gam[e] + bet[e];
    }
}

// ---------------- 5. FFN stage 1: h = relu(qm @ W1 + b1), qm computed on the fly ----------------
__global__ void ffn1_kernel(const float* __restrict__ theta, const float* __restrict__ W1,
                            const float* __restrict__ b1) {
    __shared__ float qm[NQ];
    int row = blockIdx.x;
    if (threadIdx.x < NQ)
        qm[threadIdx.x] = cosf(d_x[(size_t)row * EE + threadIdx.x]) * cosf(theta[threadIdx.x]);
    __syncthreads();
    #pragma unroll
    for (int p = 0; p < 4; p++) {
        int k = threadIdx.x + p * 256;
        float acc = b1[k];
        #pragma unroll
        for (int j = 0; j < NQ; j++)
            acc += qm[j] * W1[j * FF + k];
        d_h[(size_t)row * FF + k] = fmaxf(acc, 0.f);
    }
}

// ---------------- 6. FFN stage 2: f = h @ W2 + b2 (into d_a) ----------------
#define BM 32
#define BK 32
__global__ __launch_bounds__(256) void ffn2_kernel(const float* __restrict__ W2,
                                                   const float* __restrict__ b2) {
    __shared__ float hs[BM][BK];
    __shared__ float ws[BK][EE];
    int t = threadIdx.x;                                // thread owns output column t
    int rowBase = blockIdx.x * BM;
    float acc[BM];
    #pragma unroll
    for (int r = 0; r < BM; r++) acc[r] = 0.f;

    for (int kt = 0; kt < FF / BK; kt++) {
        __syncthreads();
        #pragma unroll
        for (int p = 0; p < 4; p++) {                   // hs: 32x32
            int idx = t + p * 256;
            hs[idx >> 5][idx & 31] =
                d_h[(size_t)(rowBase + (idx >> 5)) * FF + kt * BK + (idx & 31)];
        }
        const float4* w4 = (const float4*)(W2 + (size_t)kt * BK * EE);
        float4* ws4 = (float4*)ws;
        #pragma unroll
        for (int p = 0; p < 8; p++)                     // ws: 32x256 contiguous
            ws4[t + p * 256] = w4[t + p * 256];
        __syncthreads();

        #pragma unroll
        for (int k4 = 0; k4 < BK / 4; k4++) {
            float w0 = ws[k4 * 4 + 0][t];
            float w1 = ws[k4 * 4 + 1][t];
            float w2v = ws[k4 * 4 + 2][t];
            float w3 = ws[k4 * 4 + 3][t];
            #pragma unroll
            for (int r = 0; r < BM; r++) {
                float4 hv = *(const float4*)&hs[r][k4 * 4];
                acc[r] += hv.x * w0 + hv.y * w1 + hv.z * w2v + hv.w * w3;
            }
        }
    }
    float bb = b2[t];
    #pragma unroll
    for (int r = 0; r < BM; r++)
        d_a[(size_t)(rowBase + r) * EE + t] = acc[r] + bb;
}

// ---------------- 7. mean over S + classifier head ----------------
__global__ void head_kernel(const float* __restrict__ Wc, const float* __restrict__ bc,
                            float* __restrict__ out) {
    __shared__ float sm[1024];
    __shared__ float mean[EE];
    int b = blockIdx.x;
    int e = threadIdx.x & 255;
    int chunk = threadIdx.x >> 8;                       // 4 chunks of S/4
    float s = 0.f;
    for (int i = 0; i < SS / 4; i++) {
        int srow = chunk * (SS / 4) + i;
        s += d_x[((size_t)b * SS + srow) * EE + e];
    }
    sm[threadIdx.x] = s;
    __syncthreads();
    if (threadIdx.x < 256) {
        float tot = sm[e] + sm[e + 256] + sm[e + 512] + sm[e + 768];
        mean[e] = tot * (1.f / SS);
    }
    __syncthreads();
    if (threadIdx.x < NC) {
        float acc = bc[threadIdx.x];
        for (int ee = 0; ee < EE; ee++)
            acc += mean[ee] * Wc[ee * NC + threadIdx.x];
        out[b * NC + threadIdx.x] = acc;
    }
}

// ---------------- launch ----------------
extern "C" void kernel_launch(void* const* d_in, const int* in_sizes, int n_in,
                              void* d_out, int out_size) {
    const int*   tok   = (const int*)d_in[0];
    const float* emb   = (const float*)d_in[1];
    const float* phi   = (const float*)d_in[2];
    const float* theta = (const float*)d_in[3];
    const float* W1    = (const float*)d_in[4];
    const float* b1    = (const float*)d_in[5];
    const float* W2    = (const float*)d_in[6];
    const float* b2    = (const float*)d_in[7];
    const float* g1    = (const float*)d_in[8];
    const float* be1   = (const float*)d_in[9];
    const float* g2    = (const float*)d_in[10];
    const float* be2   = (const float*)d_in[11];
    const float* Wc    = (const float*)d_in[12];
    const float* bc    = (const float*)d_in[13];
    float* out = (float*)d_out;

    embed_kernel<<<ROWS * EE / 256, 256>>>(tok, emb);
    for (int l = 0; l < LL; l++) {
        qmap_kernel<<<ROWS * NH / 256, 256>>>(phi + l * NQ);
        attn_kernel<<<dim3(SS / 32, BB), 256>>>();
        addln_kernel<<<ROWS / 8, 256>>>(g1 + l * EE, be1 + l * EE);
        ffn1_kernel<<<ROWS, 256>>>(theta + l * NQ, W1 + (size_t)l * NQ * FF, b1 + l * FF);
        ffn2_kernel<<<ROWS / BM, 256>>>(W2 + (size_t)l * FF * EE, b2 + l * EE);
        addln_kernel<<<ROWS / 8, 256>>>(g2 + l * EE, be2 + l * EE);
    }
    head_kernel<<<BB, 1024>>>(Wc, bc, out);
}

// round 3
// speedup vs baseline: 2.5622x; 2.5622x over previous
#include <cuda_runtime.h>
#include <math.h>

#define BB 8
#define SS 2048
#define EE 256
#define LL 4
#define FF 1024
#define NQ 8
#define NC 10
#define ROWS (BB*SS)   // 16384

// ---------------- scratch (static device arrays; no allocation) ----------------
__device__ float d_x[ROWS*EE];   // activations  (16 MB)
__device__ float d_q[ROWS*EE];   // quantum-attention q, tf32-rounded (16 MB)
__device__ float d_a[ROWS*EE];   // attention out / ffn out (16 MB)

__device__ __forceinline__ float tf32rna(float x) {
    unsigned u;
    asm("cvt.rna.tf32.f32 %0, %1;" : "=r"(u) : "f"(x));
    return __uint_as_float(u);
}

#define MMA_TF32(d, a0, a1, a2, a3, b0, b1)                                   \
    asm volatile(                                                             \
        "mma.sync.aligned.m16n8k8.row.col.f32.tf32.tf32.f32 "                 \
        "{%0,%1,%2,%3}, {%4,%5,%6,%7}, {%8,%9}, {%0,%1,%2,%3};"               \
        : "+f"(d[0]), "+f"(d[1]), "+f"(d[2]), "+f"(d[3])                      \
        : "r"(a0), "r"(a1), "r"(a2), "r"(a3), "r"(b0), "r"(b1))

// ---------------- 1. embedding + positional encoding (fp32, matches reference) ----------------
__global__ void embed_kernel(const int* __restrict__ tok, const float* __restrict__ emb) {
    int gidx = blockIdx.x * blockDim.x + threadIdx.x;
    int row = gidx >> 8;
    int e = gidx & 255;
    int s = row & (SS - 1);
    float freq = expf((float)(e & ~1) * (-9.210340371976184f / 256.0f));
    float ang = (float)s * freq;
    float pe = (e & 1) ? cosf(ang) : sinf(ang);
    d_x[gidx] = emb[(size_t)tok[row] * EE + e] + pe;
}

// ---------------- 2. quantum attention q-map (tf32-rounded output) ----------------
__global__ void qmap_kernel(const float* __restrict__ phi) {
    int g = blockIdx.x * blockDim.x + threadIdx.x;      // ROWS*32 threads
    int base = g * NQ;
    float4 a0 = *(const float4*)(d_x + base);
    float4 a1 = *(const float4*)(d_x + base + 4);
    float c[8];
    c[0] = cosf(a0.x + phi[0]); c[1] = cosf(a0.y + phi[1]);
    c[2] = cosf(a0.z + phi[2]); c[3] = cosf(a0.w + phi[3]);
    c[4] = cosf(a1.x + phi[4]); c[5] = cosf(a1.y + phi[5]);
    c[6] = cosf(a1.z + phi[6]); c[7] = cosf(a1.w + phi[7]);
    float out[8];
    float t = c[1];
    #pragma unroll
    for (int j = 2; j < 8; j++) t *= c[j];
    out[0] = t;
    float pref = c[0];
    #pragma unroll
    for (int i = 1; i < 8; i++) { pref *= c[i]; out[i] = pref; }
    #pragma unroll
    for (int i = 0; i < 8; i++) out[i] = tf32rna(out[i]);
    *(float4*)(d_q + base)     = make_float4(out[0], out[1], out[2], out[3]);
    *(float4*)(d_q + base + 4) = make_float4(out[4], out[5], out[6], out[7]);
}

// ---------------- 3. tensor-core flash attention (Q = K = V = q, tf32) ----------------
// 8 warps / 64 Q rows. Warp pair (w, w^1) shares 16 rows; each owns half of E.
#define KT2 64
#define KSTRIDE 260
#define SSTRIDE 68
#define ATT_SMEM ((64 * KSTRIDE + 2 * 8 * 16 * SSTRIDE) * 4)   // 136192 B

__global__ __launch_bounds__(256, 1) void attn_mma_kernel() {
    extern __shared__ float smaf[];
    float* Ks = smaf;                        // [64][260]
    float* Sb = smaf + 64 * KSTRIDE;         // [8][16][68]
    float* Pb = Sb + 8 * 16 * SSTRIDE;       // [8][16][68]

    const int tid = threadIdx.x;
    const int w = tid >> 5, lane = tid & 31;
    const int qt = lane >> 2;                // 0..7 (row within frag)
    const int tq = lane & 3;                 // thread-in-quad
    const int eh = w & 1;                    // E half
    const int b = blockIdx.y;
    const int row0 = blockIdx.x * 64 + (w >> 1) * 16;
    const float* qb = d_q + (size_t)b * SS * EE;
    const float SCALE = 0.35355339059327373f;  // 1/sqrt(8)

    // Q A-fragments for this warp's E half (raw tf32 bits)
    unsigned qf[16][4];
    {
        const float* base = qb + (size_t)(row0 + qt) * EE + eh * 128 + tq;
        #pragma unroll
        for (int k = 0; k < 16; k++) {
            qf[k][0] = __float_as_uint(base[k * 8]);
            qf[k][1] = __float_as_uint(base[8 * EE + k * 8]);
            qf[k][2] = __float_as_uint(base[k * 8 + 4]);
            qf[k][3] = __float_as_uint(base[8 * EE + k * 8 + 4]);
        }
    }
    float o[16][4];
    #pragma unroll
    for (int n = 0; n < 16; n++) { o[n][0] = o[n][1] = o[n][2] = o[n][3] = 0.f; }
    float m0 = -1e30f, m1 = -1e30f, l0 = 0.f, l1 = 0.f;

    float* Sw = Sb + w * 16 * SSTRIDE;
    float* Sp = Sb + (w ^ 1) * 16 * SSTRIDE;
    float* Pw = Pb + w * 16 * SSTRIDE;

    for (int kt = 0; kt < SS / KT2; kt++) {
        __syncthreads();
        // cooperative K-tile load: 64x256 -> Ks[64][260]
        const float4* src = (const float4*)(qb + (size_t)kt * KT2 * EE);
        #pragma unroll
        for (int p = 0; p < 16; p++) {
            int idx = p * 256 + tid;
            int r = idx >> 6, c4 = idx & 63;
            *(float4*)(Ks + r * KSTRIDE + c4 * 4) = src[idx];
        }
        __syncthreads();

        // S_half = Q_half @ K_half^T  (16x64)
        float sc[8][4];
        #pragma unroll
        for (int n = 0; n < 8; n++) { sc[n][0] = sc[n][1] = sc[n][2] = sc[n][3] = 0.f; }
        #pragma unroll
        for (int k = 0; k < 16; k++) {
            int ek = eh * 128 + k * 8 + tq;
            #pragma unroll
            for (int n = 0; n < 8; n++) {
                unsigned b0 = __float_as_uint(Ks[(n * 8 + qt) * KSTRIDE + ek]);
                unsigned b1 = __float_as_uint(Ks[(n * 8 + qt) * KSTRIDE + ek + 4]);
                MMA_TF32(sc[n], qf[k][0], qf[k][1], qf[k][2], qf[k][3], b0, b1);
            }
        }

        // exchange halves with partner warp, apply scale
        #pragma unroll
        for (int n = 0; n < 8; n++) {
            *(float2*)(Sw + qt * SSTRIDE + n * 8 + 2 * tq)       = make_float2(sc[n][0], sc[n][1]);
            *(float2*)(Sw + (qt + 8) * SSTRIDE + n * 8 + 2 * tq) = make_float2(sc[n][2], sc[n][3]);
        }
        __syncthreads();
        #pragma unroll
        for (int n = 0; n < 8; n++) {
            float2 p0 = *(const float2*)(Sp + qt * SSTRIDE + n * 8 + 2 * tq);
            float2 p1 = *(const float2*)(Sp + (qt + 8) * SSTRIDE + n * 8 + 2 * tq);
            sc[n][0] = (sc[n][0] + p0.x) * SCALE;
            sc[n][1] = (sc[n][1] + p0.y) * SCALE;
            sc[n][2] = (sc[n][2] + p1.x) * SCALE;
            sc[n][3] = (sc[n][3] + p1.y) * SCALE;
        }

        // online softmax (rows r0 = qt, r1 = qt+8 of this warp's 16-row group)
        float mx0 = sc[0][0], mx1 = sc[0][2];
        #pragma unroll
        for (int n = 0; n < 8; n++) {
            mx0 = fmaxf(mx0, fmaxf(sc[n][0], sc[n][1]));
            mx1 = fmaxf(mx1, fmaxf(sc[n][2], sc[n][3]));
        }
        mx0 = fmaxf(mx0, __shfl_xor_sync(0xffffffffu, mx0, 1));
        mx0 = fmaxf(mx0, __shfl_xor_sync(0xffffffffu, mx0, 2));
        mx1 = fmaxf(mx1, __shfl_xor_sync(0xffffffffu, mx1, 1));
        mx1 = fmaxf(mx1, __shfl_xor_sync(0xffffffffu, mx1, 2));
        float nm0 = fmaxf(m0, mx0), nm1 = fmaxf(m1, mx1);
        float c0 = __expf(m0 - nm0), c1 = __expf(m1 - nm1);
        m0 = nm0; m1 = nm1; l0 *= c0; l1 *= c1;
        #pragma unroll
        for (int n = 0; n < 16; n++) {
            o[n][0] *= c0; o[n][1] *= c0; o[n][2] *= c1; o[n][3] *= c1;
        }
        float s0 = 0.f, s1 = 0.f;
        #pragma unroll
        for (int n = 0; n < 8; n++) {
            sc[n][0] = tf32rna(__expf(sc[n][0] - m0));
            sc[n][1] = tf32rna(__expf(sc[n][1] - m0));
            sc[n][2] = tf32rna(__expf(sc[n][2] - m1));
            sc[n][3] = tf32rna(__expf(sc[n][3] - m1));
            s0 += sc[n][0] + sc[n][1];
            s1 += sc[n][2] + sc[n][3];
        }
        s0 += __shfl_xor_sync(0xffffffffu, s0, 1);
        s0 += __shfl_xor_sync(0xffffffffu, s0, 2);
        s1 += __shfl_xor_sync(0xffffffffu, s1, 1);
        s1 += __shfl_xor_sync(0xffffffffu, s1, 2);
        l0 += s0; l1 += s1;

        // stage P through smem to get A-fragment layout
        #pragma unroll
        for (int n = 0; n < 8; n++) {
            *(float2*)(Pw + qt * SSTRIDE + n * 8 + 2 * tq)       = make_float2(sc[n][0], sc[n][1]);
            *(float2*)(Pw + (qt + 8) * SSTRIDE + n * 8 + 2 * tq) = make_float2(sc[n][2], sc[n][3]);
        }
        __syncthreads();

        // O_half += P @ V_half   (V = same K tile, transposed access)
        #pragma unroll
        for (int k = 0; k < 8; k++) {
            unsigned a0 = __float_as_uint(Pw[qt * SSTRIDE + k * 8 + tq]);
            unsigned a1 = __float_as_uint(Pw[(qt + 8) * SSTRIDE + k * 8 + tq]);
            unsigned a2 = __float_as_uint(Pw[qt * SSTRIDE + k * 8 + tq + 4]);
            unsigned a3 = __float_as_uint(Pw[(qt + 8) * SSTRIDE + k * 8 + tq + 4]);
            #pragma unroll
            for (int n = 0; n < 16; n++) {
                int ev = eh * 128 + n * 8 + qt;
                unsigned b0 = __float_as_uint(Ks[(k * 8 + tq) * KSTRIDE + ev]);
                unsigned b1 = __float_as_uint(Ks[(k * 8 + tq + 4) * KSTRIDE + ev]);
                MMA_TF32(o[n], a0, a1, a2, a3, b0, b1);
            }
        }
    }

    // write O / l
    float i0 = 1.f / l0, i1 = 1.f / l1;
    float* outp = d_a + ((size_t)b * SS + row0) * EE;
    #pragma unroll
    for (int n = 0; n < 16; n++) {
        int col = eh * 128 + n * 8 + 2 * tq;
        *(float2*)(outp + (size_t)qt * EE + col)       = make_float2(o[n][0] * i0, o[n][1] * i0);
        *(float2*)(outp + (size_t)(qt + 8) * EE + col) = make_float2(o[n][2] * i1, o[n][3] * i1);
    }
}

// ---------------- 4. x = LayerNorm(x + a) ----------------
__global__ void addln_kernel(const float* __restrict__ gam, const float* __restrict__ bet) {
    int warp = threadIdx.x >> 5, lane = threadIdx.x & 31;
    int row = blockIdx.x * 8 + warp;
    float* xr = d_x + (size_t)row * EE;
    const float* fr = d_a + (size_t)row * EE;
    float v[8];
    float sum = 0.f, sq = 0.f;
    #pragma unroll
    for (int i = 0; i < 8; i++) {
        int e = lane + 32 * i;
        v[i] = xr[e] + fr[e];
        sum += v[i];
        sq += v[i] * v[i];
    }
    #pragma unroll
    for (int mask = 16; mask >= 1; mask >>= 1) {
        sum += __shfl_xor_sync(0xffffffffu, sum, mask);
        sq  += __shfl_xor_sync(0xffffffffu, sq, mask);
    }
    float mean = sum * (1.f / EE);
    float var = sq * (1.f / EE) - mean * mean;
    float inv = rsqrtf(var + 1e-5f);
    #pragma unroll
    for (int i = 0; i < 8; i++) {
        int e = lane + 32 * i;
        xr[e] = (v[i] - mean) * inv * gam[e] + bet[e];
    }
}

// ---------------- 5. fused FFN: f = relu(qm @ W1 + b1) @ W2 + b2 ----------------
#define BM 32
#define BK 32
__global__ __launch_bounds__(256) void ffn2_kernel(const float* __restrict__ theta,
                                                   const float* __restrict__ W1,
                                                   const float* __restrict__ b1,
                                                   const float* __restrict__ W2,
                                                   const float* __restrict__ b2) {
    __shared__ float qm[BM][9];
    __shared__ float w1s[NQ][BK];
    __shared__ float hs[BM][BK];
    __shared__ float ws[BK][EE];
    int t = threadIdx.x;
    int rowBase = blockIdx.x * BM;

    if (t < BM * NQ) {
        int r = t >> 3, j = t & 7;
        qm[r][j] = cosf(d_x[(size_t)(rowBase + r) * EE + j]) * cosf(theta[j]);
    }

    float acc[BM];
    #pragma unroll
    for (int r = 0; r < BM; r++) acc[r] = 0.f;

    for (int kt = 0; kt < FF / BK; kt++) {
        __syncthreads();
        {   // W1 tile 8x32
            int j = t >> 5, k = t & 31;
            w1s[j][k] = W1[j * FF + kt * BK + k];
        }
        const float4* w4 = (const float4*)(W2 + (size_t)kt * BK * EE);
        float4* ws4 = (float4*)ws;
        #pragma unroll
        for (int p = 0; p < 8; p++)
            ws4[t + p * 256] = w4[t + p * 256];
        __syncthreads();
        {   // hidden tile 32x32, computed in-block
            int r = t >> 3, kb = (t & 7) * 4;
            const float* b1g = b1 + kt * BK;
            #pragma unroll
            for (int i = 0; i < 4; i++) {
                float h = b1g[kb + i];
                #pragma unroll
                for (int j = 0; j < NQ; j++)
                    h += qm[r][j] * w1s[j][kb + i];
                hs[r][kb + i] = fmaxf(h, 0.f);
            }
        }
        __syncthreads();

        #pragma unroll
        for (int k4 = 0; k4 < BK / 4; k4++) {
            float w0 = ws[k4 * 4 + 0][t];
            float w1v = ws[k4 * 4 + 1][t];
            float w2v = ws[k4 * 4 + 2][t];
            float w3 = ws[k4 * 4 + 3][t];
            #pragma unroll
            for (int r = 0; r < BM; r++) {
                float4 hv = *(const float4*)&hs[r][k4 * 4];
                acc[r] += hv.x * w0 + hv.y * w1v + hv.z * w2v + hv.w * w3;
            }
        }
    }
    float bb = b2[t];
    #pragma unroll
    for (int r = 0; r < BM; r++)
        d_a[(size_t)(rowBase + r) * EE + t] = acc[r] + bb;
}

// ---------------- 6. mean over S + classifier head ----------------
__global__ void head_kernel(const float* __restrict__ Wc, const float* __restrict__ bc,
                            float* __restrict__ out) {
    __shared__ float sm[1024];
    __shared__ float mean[EE];
    int b = blockIdx.x;
    int e = threadIdx.x & 255;
    int chunk = threadIdx.x >> 8;
    float s = 0.f;
    for (int i = 0; i < SS / 4; i++) {
        int srow = chunk * (SS / 4) + i;
        s += d_x[((size_t)b * SS + srow) * EE + e];
    }
    sm[threadIdx.x] = s;
    __syncthreads();
    if (threadIdx.x < 256) {
        float tot = sm[e] + sm[e + 256] + sm[e + 512] + sm[e + 768];
        mean[e] = tot * (1.f / SS);
    }
    __syncthreads();
    if (threadIdx.x < NC) {
        float acc = bc[threadIdx.x];
        for (int ee = 0; ee < EE; ee++)
            acc += mean[ee] * Wc[ee * NC + threadIdx.x];
        out[b * NC + threadIdx.x] = acc;
    }
}

// ---------------- launch ----------------
extern "C" void kernel_launch(void* const* d_in, const int* in_sizes, int n_in,
                              void* d_out, int out_size) {
    const int*   tok   = (const int*)d_in[0];
    const float* emb   = (const float*)d_in[1];
    const float* phi   = (const float*)d_in[2];
    const float* theta = (const float*)d_in[3];
    const float* W1    = (const float*)d_in[4];
    const float* b1    = (const float*)d_in[5];
    const float* W2    = (const float*)d_in[6];
    const float* b2    = (const float*)d_in[7];
    const float* g1    = (const float*)d_in[8];
    const float* be1   = (const float*)d_in[9];
    const float* g2    = (const float*)d_in[10];
    const float* be2   = (const float*)d_in[11];
    const float* Wc    = (const float*)d_in[12];
    const float* bc    = (const float*)d_in[13];
    float* out = (float*)d_out;

    cudaFuncSetAttribute(attn_mma_kernel,
                         cudaFuncAttributeMaxDynamicSharedMemorySize, ATT_SMEM);

    embed_kernel<<<ROWS * EE / 256, 256>>>(tok, emb);
    for (int l = 0; l < LL; l++) {
        qmap_kernel<<<ROWS * 32 / 256, 256>>>(phi + l * NQ);
        attn_mma_kernel<<<dim3(SS / 64, BB), 256, ATT_SMEM>>>();
        addln_kernel<<<ROWS / 8, 256>>>(g1 + l * EE, be1 + l * EE);
        ffn2_kernel<<<ROWS / BM, 256>>>(theta + l * NQ, W1 + (size_t)l * NQ * FF,
                                        b1 + l * FF, W2 + (size_t)l * FF * EE, b2 + l * EE);
        addln_kernel<<<ROWS / 8, 256>>>(g2 + l * EE, be2 + l * EE);
    }
    head_kernel<<<BB, 1024>>>(Wc, bc, out);
}

// round 4
// speedup vs baseline: 6.5450x; 2.5544x over previous
#include <cuda_runtime.h>
#include <cuda_bf16.h>
#include <math.h>

#define BB 8
#define SS 2048
#define EE 256
#define LL 4
#define FF 1024
#define NQ 8
#define NC 10
#define ROWS (BB*SS)   // 16384

// ---------------- scratch (static device arrays; no allocation) ----------------
__device__ float d_x[ROWS*EE];                 // activations  (16 MB)
__device__ __nv_bfloat16 d_qb[ROWS*EE];        // quantum q, bf16 (8 MB)
__device__ float d_a[ROWS*EE];                 // attention out / ffn out (16 MB)

#define MMA_BF16(d, a0, a1, a2, a3, b0, b1)                                   \
    asm volatile(                                                             \
        "mma.sync.aligned.m16n8k16.row.col.f32.bf16.bf16.f32 "                \
        "{%0,%1,%2,%3}, {%4,%5,%6,%7}, {%8,%9}, {%0,%1,%2,%3};"               \
        : "+f"(d[0]), "+f"(d[1]), "+f"(d[2]), "+f"(d[3])                      \
        : "r"(a0), "r"(a1), "r"(a2), "r"(a3), "r"(b0), "r"(b1))

#define MMA_TF32(d, a0, a1, a2, a3, b0, b1)                                   \
    asm volatile(                                                             \
        "mma.sync.aligned.m16n8k8.row.col.f32.tf32.tf32.f32 "                 \
        "{%0,%1,%2,%3}, {%4,%5,%6,%7}, {%8,%9}, {%0,%1,%2,%3};"               \
        : "+f"(d[0]), "+f"(d[1]), "+f"(d[2]), "+f"(d[3])                      \
        : "r"(a0), "r"(a1), "r"(a2), "r"(a3), "r"(b0), "r"(b1))

__device__ __forceinline__ void ldsm4(unsigned& r0, unsigned& r1, unsigned& r2,
                                      unsigned& r3, unsigned a) {
    asm volatile("ldmatrix.sync.aligned.m8n8.x4.shared.b16 {%0,%1,%2,%3}, [%4];"
                 : "=r"(r0), "=r"(r1), "=r"(r2), "=r"(r3) : "r"(a));
}
__device__ __forceinline__ void ldsm4t(unsigned& r0, unsigned& r1, unsigned& r2,
                                       unsigned& r3, unsigned a) {
    asm volatile("ldmatrix.sync.aligned.m8n8.x4.trans.shared.b16 {%0,%1,%2,%3}, [%4];"
                 : "=r"(r0), "=r"(r1), "=r"(r2), "=r"(r3) : "r"(a));
}

// q-map math: c_j = cos(v_j + phi_j); q_0 = prod_{j>=1} c_j; q_i = prod_{j<=i} c_j
__device__ __forceinline__ void qmap8(const float* v, const float* phi, float* out) {
    float c[8];
    #pragma unroll
    for (int i = 0; i < 8; i++) c[i] = cosf(v[i] + phi[i]);
    float t = c[1];
    #pragma unroll
    for (int j = 2; j < 8; j++) t *= c[j];
    out[0] = t;
    float pref = c[0];
    #pragma unroll
    for (int i = 1; i < 8; i++) { pref *= c[i]; out[i] = pref; }
}

__device__ __forceinline__ void store_q8(__nv_bfloat16* qp, const float* out) {
    __nv_bfloat162* q2 = (__nv_bfloat162*)qp;
    q2[0] = __float22bfloat162_rn(make_float2(out[0], out[1]));
    q2[1] = __float22bfloat162_rn(make_float2(out[2], out[3]));
    q2[2] = __float22bfloat162_rn(make_float2(out[4], out[5]));
    q2[3] = __float22bfloat162_rn(make_float2(out[6], out[7]));
}

// ---------------- 1. embedding + PE + layer-0 q (fused) ----------------
__global__ void embed_q_kernel(const int* __restrict__ tok, const float* __restrict__ emb,
                               const float* __restrict__ phi) {
    int g = blockIdx.x * blockDim.x + threadIdx.x;   // ROWS*32: (row, head)
    int row = g >> 5, h = g & 31;
    int s = row & (SS - 1);
    int base = row * EE + h * 8;
    const float4* er = (const float4*)(emb + (size_t)tok[row] * EE + h * 8);
    float4 e0 = er[0], e1 = er[1];
    float v[8] = {e0.x, e0.y, e0.z, e0.w, e1.x, e1.y, e1.z, e1.w};
    #pragma unroll
    for (int i = 0; i < 8; i++) {
        int e = h * 8 + i;
        float freq = expf((float)(e & ~1) * (-9.210340371976184f / 256.0f));
        float ang = (float)s * freq;
        v[i] += (e & 1) ? cosf(ang) : sinf(ang);
    }
    *(float4*)(d_x + base)     = make_float4(v[0], v[1], v[2], v[3]);
    *(float4*)(d_x + base + 4) = make_float4(v[4], v[5], v[6], v[7]);
    float out[8];
    qmap8(v, phi, out);
    store_q8(d_qb + base, out);
}

// ---------------- 2. bf16 tensor-core flash attention (Q = K = V = q) ----------------
// 8 warps / 64 Q rows; warp pair (w, w^1) shares 16 rows, each owns E half.
#define KP 264                       // Ks row stride (bf16)
#define SST 68                       // Sb row stride (fp32)
#define PP 72                        // Pb row stride (bf16)
#define KS_BYTES (64 * KP * 2)       // 33792
#define SB_OFF KS_BYTES
#define SB_BYTES (8 * 16 * SST * 4)  // 34816
#define PB_OFF (SB_OFF + SB_BYTES)   // 68608
#define ATT_SMEM (PB_OFF + 8 * 16 * PP * 2)  // 87040

__global__ __launch_bounds__(256, 1) void attn_kernel() {
    extern __shared__ char smc[];
    __nv_bfloat16* Ks = (__nv_bfloat16*)smc;
    float* Sb = (float*)(smc + SB_OFF);
    __nv_bfloat16* Pb = (__nv_bfloat16*)(smc + PB_OFF);
    const unsigned ks_s = (unsigned)__cvta_generic_to_shared(Ks);

    const int tid = threadIdx.x;
    const int w = tid >> 5, lane = tid & 31;
    const int qt = lane >> 2, tq = lane & 3;
    const int eh = w & 1;
    const int b = blockIdx.y;
    const int row0 = blockIdx.x * 64 + (w >> 1) * 16;
    const __nv_bfloat16* qbb = d_qb + (size_t)b * SS * EE;
    const float SCALE = 0.35355339059327373f;   // 1/sqrt(8)

    // Q A-fragments (bf16x2 regs), 8 ksteps covering this warp's E half
    unsigned qa[8][4];
    {
        const __nv_bfloat16* p0 = qbb + (size_t)(row0 + qt) * EE + eh * 128 + 2 * tq;
        #pragma unroll
        for (int k = 0; k < 8; k++) {
            qa[k][0] = *(const unsigned*)(p0 + 16 * k);
            qa[k][1] = *(const unsigned*)(p0 + 8 * EE + 16 * k);
            qa[k][2] = *(const unsigned*)(p0 + 16 * k + 8);
            qa[k][3] = *(const unsigned*)(p0 + 8 * EE + 16 * k + 8);
        }
    }
    float o[16][4];
    #pragma unroll
    for (int n = 0; n < 16; n++) { o[n][0] = o[n][1] = o[n][2] = o[n][3] = 0.f; }
    float m0 = -1e30f, m1 = -1e30f, l0 = 0.f, l1 = 0.f;

    float* Sw = Sb + w * 16 * SST;
    float* Sp = Sb + (w ^ 1) * 16 * SST;
    __nv_bfloat16* Pw = Pb + w * 16 * PP;

    // LDSM lane-address bases (bytes)
    const int l7 = lane & 7, l3 = lane >> 3;
    const unsigned qk_base = ks_s + 2u * (unsigned)(l7 * KP + eh * 128 + 8 * l3);
    const unsigned pv_base = ks_s + 2u * (unsigned)((l7 + 8 * (l3 & 1)) * KP +
                                                    eh * 128 + 8 * (l3 >> 1));

    for (int kt = 0; kt < SS / 64; kt++) {
        __syncthreads();
        // cooperative K-tile load: 64x256 bf16 -> Ks[64][KP]
        const uint4* src = (const uint4*)(qbb + (size_t)kt * 64 * EE);
        #pragma unroll
        for (int p = 0; p < 8; p++) {
            int idx = p * 256 + tid;
            int r = idx >> 5, c8 = idx & 31;
            *(uint4*)(Ks + r * KP + c8 * 8) = src[idx];
        }
        __syncthreads();

        // S_half = Q_half @ K_half^T  (16x64)
        float sc[8][4];
        #pragma unroll
        for (int n = 0; n < 8; n++) { sc[n][0] = sc[n][1] = sc[n][2] = sc[n][3] = 0.f; }
        #pragma unroll
        for (int n = 0; n < 8; n++) {
            unsigned base = qk_base + (unsigned)(n * 8 * KP * 2);
            #pragma unroll
            for (int kk = 0; kk < 4; kk++) {
                unsigned b0, b1, b2, b3;
                ldsm4(b0, b1, b2, b3, base + kk * 64);
                MMA_BF16(sc[n], qa[2*kk][0], qa[2*kk][1], qa[2*kk][2], qa[2*kk][3], b0, b1);
                MMA_BF16(sc[n], qa[2*kk+1][0], qa[2*kk+1][1], qa[2*kk+1][2], qa[2*kk+1][3], b2, b3);
            }
        }

        // exchange halves with partner warp, apply scale
        #pragma unroll
        for (int n = 0; n < 8; n++) {
            *(float2*)(Sw + qt * SST + n * 8 + 2 * tq)       = make_float2(sc[n][0], sc[n][1]);
            *(float2*)(Sw + (qt + 8) * SST + n * 8 + 2 * tq) = make_float2(sc[n][2], sc[n][3]);
        }
        __syncthreads();
        #pragma unroll
        for (int n = 0; n < 8; n++) {
            float2 p0 = *(const float2*)(Sp + qt * SST + n * 8 + 2 * tq);
            float2 p1 = *(const float2*)(Sp + (qt + 8) * SST + n * 8 + 2 * tq);
            sc[n][0] = (sc[n][0] + p0.x) * SCALE;
            sc[n][1] = (sc[n][1] + p0.y) * SCALE;
            sc[n][2] = (sc[n][2] + p1.x) * SCALE;
            sc[n][3] = (sc[n][3] + p1.y) * SCALE;
        }

        // online softmax
        float mx0 = sc[0][0], mx1 = sc[0][2];
        #pragma unroll
        for (int n = 0; n < 8; n++) {
            mx0 = fmaxf(mx0, fmaxf(sc[n][0], sc[n][1]));
            mx1 = fmaxf(mx1, fmaxf(sc[n][2], sc[n][3]));
        }
        mx0 = fmaxf(mx0, __shfl_xor_sync(0xffffffffu, mx0, 1));
        mx0 = fmaxf(mx0, __shfl_xor_sync(0xffffffffu, mx0, 2));
        mx1 = fmaxf(mx1, __shfl_xor_sync(0xffffffffu, mx1, 1));
        mx1 = fmaxf(mx1, __shfl_xor_sync(0xffffffffu, mx1, 2));
        float nm0 = fmaxf(m0, mx0), nm1 = fmaxf(m1, mx1);
        float c0 = __expf(m0 - nm0), c1 = __expf(m1 - nm1);
        m0 = nm0; m1 = nm1; l0 *= c0; l1 *= c1;
        #pragma unroll
        for (int n = 0; n < 16; n++) {
            o[n][0] *= c0; o[n][1] *= c0; o[n][2] *= c1; o[n][3] *= c1;
        }
        // P = exp(S - m), bf16-rounded (l accumulated from the ROUNDED values)
        float s0 = 0.f, s1 = 0.f;
        #pragma unroll
        for (int n = 0; n < 8; n++) {
            float e00 = __expf(sc[n][0] - m0), e01 = __expf(sc[n][1] - m0);
            float e10 = __expf(sc[n][2] - m1), e11 = __expf(sc[n][3] - m1);
            __nv_bfloat162 h0 = __float22bfloat162_rn(make_float2(e00, e01));
            __nv_bfloat162 h1 = __float22bfloat162_rn(make_float2(e10, e11));
            *(__nv_bfloat162*)(Pw + qt * PP + n * 8 + 2 * tq)       = h0;
            *(__nv_bfloat162*)(Pw + (qt + 8) * PP + n * 8 + 2 * tq) = h1;
            s0 += __bfloat162float(h0.x) + __bfloat162float(h0.y);
            s1 += __bfloat162float(h1.x) + __bfloat162float(h1.y);
        }
        s0 += __shfl_xor_sync(0xffffffffu, s0, 1);
        s0 += __shfl_xor_sync(0xffffffffu, s0, 2);
        s1 += __shfl_xor_sync(0xffffffffu, s1, 1);
        s1 += __shfl_xor_sync(0xffffffffu, s1, 2);
        l0 += s0; l1 += s1;
        __syncwarp();

        // P A-fragments
        unsigned pa[4][4];
        #pragma unroll
        for (int k = 0; k < 4; k++) {
            int k0 = k * 16;
            pa[k][0] = *(const unsigned*)(Pw + qt * PP + k0 + 2 * tq);
            pa[k][1] = *(const unsigned*)(Pw + (qt + 8) * PP + k0 + 2 * tq);
            pa[k][2] = *(const unsigned*)(Pw + qt * PP + k0 + 2 * tq + 8);
            pa[k][3] = *(const unsigned*)(Pw + (qt + 8) * PP + k0 + 2 * tq + 8);
        }
        // O_half += P @ V_half  (V = same K tile, ldmatrix.trans)
        #pragma unroll
        for (int np = 0; np < 8; np++) {
            unsigned base = pv_base + (unsigned)(np * 32);
            #pragma unroll
            for (int k = 0; k < 4; k++) {
                unsigned b0, b1, b2, b3;
                ldsm4t(b0, b1, b2, b3, base + (unsigned)(k * 16 * KP * 2));
                MMA_BF16(o[2*np],   pa[k][0], pa[k][1], pa[k][2], pa[k][3], b0, b1);
                MMA_BF16(o[2*np+1], pa[k][0], pa[k][1], pa[k][2], pa[k][3], b2, b3);
            }
        }
    }

    // write O
    float i0 = 1.f / l0, i1 = 1.f / l1;
    float* outp = d_a + ((size_t)b * SS + row0) * EE;
    #pragma unroll
    for (int n = 0; n < 16; n++) {
        int col = eh * 128 + n * 8 + 2 * tq;
        *(float2*)(outp + (size_t)qt * EE + col)       = make_float2(o[n][0] * i0, o[n][1] * i0);
        *(float2*)(outp + (size_t)(qt + 8) * EE + col) = make_float2(o[n][2] * i1, o[n][3] * i1);
    }
}

// ---------------- 3. x = LayerNorm(x + a), optional fused q for next layer ----------------
// lane owns 8 contiguous e (= one head) -> q prefix-product is thread-local
__global__ void addln_kernel(const float* __restrict__ gam, const float* __restrict__ bet,
                             const float* __restrict__ phi) {
    int warp = threadIdx.x >> 5, lane = threadIdx.x & 31;
    int row = blockIdx.x * 8 + warp;
    int base = row * EE + lane * 8;
    float4 x0 = *(float4*)(d_x + base), x1 = *(float4*)(d_x + base + 4);
    float4 f0 = *(const float4*)(d_a + base), f1 = *(const float4*)(d_a + base + 4);
    float v[8] = {x0.x + f0.x, x0.y + f0.y, x0.z + f0.z, x0.w + f0.w,
                  x1.x + f1.x, x1.y + f1.y, x1.z + f1.z, x1.w + f1.w};
    float sum = 0.f, sq = 0.f;
    #pragma unroll
    for (int i = 0; i < 8; i++) { sum += v[i]; sq += v[i] * v[i]; }
    #pragma unroll
    for (int mask = 16; mask >= 1; mask >>= 1) {
        sum += __shfl_xor_sync(0xffffffffu, sum, mask);
        sq  += __shfl_xor_sync(0xffffffffu, sq, mask);
    }
    float mean = sum * (1.f / EE);
    float var = sq * (1.f / EE) - mean * mean;
    float inv = rsqrtf(var + 1e-5f);
    float4 g0 = *(const float4*)(gam + lane * 8), g1v = *(const float4*)(gam + lane * 8 + 4);
    float4 b0 = *(const float4*)(bet + lane * 8), b1v = *(const float4*)(bet + lane * 8 + 4);
    float gv[8] = {g0.x, g0.y, g0.z, g0.w, g1v.x, g1v.y, g1v.z, g1v.w};
    float bv[8] = {b0.x, b0.y, b0.z, b0.w, b1v.x, b1v.y, b1v.z, b1v.w};
    #pragma unroll
    for (int i = 0; i < 8; i++) v[i] = (v[i] - mean) * inv * gv[i] + bv[i];
    *(float4*)(d_x + base)     = make_float4(v[0], v[1], v[2], v[3]);
    *(float4*)(d_x + base + 4) = make_float4(v[4], v[5], v[6], v[7]);
    if (phi) {
        float out[8];
        qmap8(v, phi, out);
        store_q8(d_qb + base, out);
    }
}

// ---------------- 4. fused FFN on tensor cores (tf32) ----------------
// CTA: 64 rows x 256 cols; warp = 32 rows x 64 cols
__global__ __launch_bounds__(256, 2) void ffn_kernel(const float* __restrict__ theta,
                                                     const float* __restrict__ W1,
                                                     const float* __restrict__ b1,
                                                     const float* __restrict__ W2,
                                                     const float* __restrict__ b2) {
    __shared__ float qm[64][9];
    __shared__ float w1s[8][33];
    __shared__ float hs[64][36];
    __shared__ float ws[32][264];
    __shared__ float b2s[256];
    const int t = threadIdx.x, w = t >> 5, lane = t & 31;
    const int qt = lane >> 2, tq = lane & 3;
    const int wm = w >> 2, wn = w & 3;
    const int rowBase = blockIdx.x * 64;

    b2s[t] = b2[t];
    #pragma unroll
    for (int i = 0; i < 2; i++) {
        int idx = t * 2 + i;
        int r = idx >> 3, j = idx & 7;
        qm[r][j] = cosf(d_x[(size_t)(rowBase + r) * EE + j]) * cosf(theta[j]);
    }

    float c[2][8][4];
    #pragma unroll
    for (int mt = 0; mt < 2; mt++)
        #pragma unroll
        for (int nt = 0; nt < 8; nt++)
            c[mt][nt][0] = c[mt][nt][1] = c[mt][nt][2] = c[mt][nt][3] = 0.f;

    for (int kt = 0; kt < FF / 32; kt++) {
        int k0g = kt * 32;
        __syncthreads();
        w1s[t >> 5][t & 31] = W1[(t >> 5) * FF + k0g + (t & 31)];
        const float4* w4 = (const float4*)(W2 + (size_t)k0g * EE);
        #pragma unroll
        for (int p = 0; p < 8; p++) {
            int idx = p * 256 + t;
            int r = idx >> 6, c4 = idx & 63;
            *(float4*)(&ws[r][c4 * 4]) = w4[idx];
        }
        __syncthreads();
        {   // hidden tile 64x32 via fused ffn1
            int r = t & 63, cg = (t >> 6) * 8;
            #pragma unroll
            for (int i = 0; i < 8; i++) {
                int cc = cg + i;
                float h = b1[k0g + cc];
                #pragma unroll
                for (int j = 0; j < 8; j++) h += qm[r][j] * w1s[j][cc];
                hs[r][cc] = fmaxf(h, 0.f);
            }
        }
        __syncthreads();
        #pragma unroll
        for (int ks = 0; ks < 4; ks++) {
            int k0 = ks * 8;
            unsigned a[2][4];
            #pragma unroll
            for (int mt = 0; mt < 2; mt++) {
                int mrow = wm * 32 + mt * 16;
                a[mt][0] = __float_as_uint(hs[mrow + qt][k0 + tq]);
                a[mt][1] = __float_as_uint(hs[mrow + qt + 8][k0 + tq]);
                a[mt][2] = __float_as_uint(hs[mrow + qt][k0 + tq + 4]);
                a[mt][3] = __float_as_uint(hs[mrow + qt + 8][k0 + tq + 4]);
            }
            #pragma unroll
            for (int nt = 0; nt < 8; nt++) {
                int n0 = wn * 64 + nt * 8;
                unsigned bb0 = __float_as_uint(ws[k0 + tq][n0 + qt]);
                unsigned bb1 = __float_as_uint(ws[k0 + tq + 4][n0 + qt]);
                MMA_TF32(c[0][nt], a[0][0], a[0][1], a[0][2], a[0][3], bb0, bb1);
                MMA_TF32(c[1][nt], a[1][0], a[1][1], a[1][2], a[1][3], bb0, bb1);
            }
        }
    }
    #pragma unroll
    for (int mt = 0; mt < 2; mt++) {
        int gr = rowBase + wm * 32 + mt * 16;
        #pragma unroll
        for (int nt = 0; nt < 8; nt++) {
            int col = wn * 64 + nt * 8 + 2 * tq;
            float bb0 = b2s[col], bb1 = b2s[col + 1];
            *(float2*)(d_a + (size_t)(gr + qt) * EE + col) =
                make_float2(c[mt][nt][0] + bb0, c[mt][nt][1] + bb1);
            *(float2*)(d_a + (size_t)(gr + qt + 8) * EE + col) =
                make_float2(c[mt][nt][2] + bb0, c[mt][nt][3] + bb1);
        }
    }
}

// ---------------- 5. mean over S + classifier head ----------------
__global__ void head_kernel(const float* __restrict__ Wc, const float* __restrict__ bc,
                            float* __restrict__ out) {
    __shared__ float sm[1024];
    __shared__ float mean[EE];
    int b = blockIdx.x;
    int e = threadIdx.x & 255;
    int chunk = threadIdx.x >> 8;
    float s = 0.f;
    for (int i = 0; i < SS / 4; i++) {
        int srow = chunk * (SS / 4) + i;
        s += d_x[((size_t)b * SS + srow) * EE + e];
    }
    sm[threadIdx.x] = s;
    __syncthreads();
    if (threadIdx.x < 256) {
        float tot = sm[e] + sm[e + 256] + sm[e + 512] + sm[e + 768];
        mean[e] = tot * (1.f / SS);
    }
    __syncthreads();
    if (threadIdx.x < NC) {
        float acc = bc[threadIdx.x];
        for (int ee = 0; ee < EE; ee++)
            acc += mean[ee] * Wc[ee * NC + threadIdx.x];
        out[b * NC + threadIdx.x] = acc;
    }
}

// ---------------- launch ----------------
extern "C" void kernel_launch(void* const* d_in, const int* in_sizes, int n_in,
                              void* d_out, int out_size) {
    const int*   tok   = (const int*)d_in[0];
    const float* emb   = (const float*)d_in[1];
    const float* phi   = (const float*)d_in[2];
    const float* theta = (const float*)d_in[3];
    const float* W1    = (const float*)d_in[4];
    const float* b1    = (const float*)d_in[5];
    const float* W2    = (const float*)d_in[6];
    const float* b2    = (const float*)d_in[7];
    const float* g1    = (const float*)d_in[8];
    const float* be1   = (const float*)d_in[9];
    const float* g2    = (const float*)d_in[10];
    const float* be2   = (const float*)d_in[11];
    const float* Wc    = (const float*)d_in[12];
    const float* bc    = (const float*)d_in[13];
    float* out = (float*)d_out;

    cudaFuncSetAttribute(attn_kernel, cudaFuncAttributeMaxDynamicSharedMemorySize, ATT_SMEM);

    embed_q_kernel<<<ROWS * 32 / 256, 256>>>(tok, emb, phi);
    for (int l = 0; l < LL; l++) {
        attn_kernel<<<dim3(SS / 64, BB), 256, ATT_SMEM>>>();
        addln_kernel<<<ROWS / 8, 256>>>(g1 + l * EE, be1 + l * EE, nullptr);
        ffn_kernel<<<ROWS / 64, 256>>>(theta + l * NQ, W1 + (size_t)l * NQ * FF,
                                       b1 + l * FF, W2 + (size_t)l * FF * EE, b2 + l * EE);
        addln_kernel<<<ROWS / 8, 256>>>(g2 + l * EE, be2 + l * EE,
                                        (l < LL - 1) ? (phi + (l + 1) * NQ) : nullptr);
    }
    head_kernel<<<BB, 1024>>>(Wc, bc, out);
}

// round 6
// speedup vs baseline: 7.3512x; 1.1232x over previous
#include <cuda_runtime.h>
#include <cuda_fp16.h>
#include <math.h>

#define BB 8
#define SS 2048
#define EE 256
#define LL 4
#define FF 1024
#define NQ 8
#define NC 10
#define ROWS (BB*SS)   // 16384

// ---------------- scratch (static device arrays; no allocation) ----------------
__device__ float d_x[ROWS*EE];            // activations  (16 MB)
__device__ __half d_qh[ROWS*EE];          // quantum q, fp16 (8 MB)
__device__ float d_a[ROWS*EE];            // attention out / ffn out (16 MB)
__device__ __half d_w2h[LL*FF*EE];        // fp16 copy of W2 (4 MB)

#define MMA_F16(d, a0, a1, a2, a3, b0, b1)                                    \
    asm volatile(                                                             \
        "mma.sync.aligned.m16n8k16.row.col.f32.f16.f16.f32 "                  \
        "{%0,%1,%2,%3}, {%4,%5,%6,%7}, {%8,%9}, {%0,%1,%2,%3};"               \
        : "+f"(d[0]), "+f"(d[1]), "+f"(d[2]), "+f"(d[3])                      \
        : "r"(a0), "r"(a1), "r"(a2), "r"(a3), "r"(b0), "r"(b1))

__device__ __forceinline__ void ldsm4(unsigned& r0, unsigned& r1, unsigned& r2,
                                      unsigned& r3, unsigned a) {
    asm volatile("ldmatrix.sync.aligned.m8n8.x4.shared.b16 {%0,%1,%2,%3}, [%4];"
                 : "=r"(r0), "=r"(r1), "=r"(r2), "=r"(r3) : "r"(a));
}
__device__ __forceinline__ void ldsm4t(unsigned& r0, unsigned& r1, unsigned& r2,
                                       unsigned& r3, unsigned a) {
    asm volatile("ldmatrix.sync.aligned.m8n8.x4.trans.shared.b16 {%0,%1,%2,%3}, [%4];"
                 : "=r"(r0), "=r"(r1), "=r"(r2), "=r"(r3) : "r"(a));
}
__device__ __forceinline__ void cpasync16(unsigned dst, const void* src) {
    asm volatile("cp.async.cg.shared.global [%0], [%1], 16;" :: "r"(dst), "l"(src));
}
#define CP_COMMIT() asm volatile("cp.async.commit_group;" ::: "memory")
#define CP_WAIT1()  asm volatile("cp.async.wait_group 1;" ::: "memory")

// q-map: c_j = cos(v_j + phi_j); q_0 = prod_{j>=1} c_j; q_i = prod_{j<=i} c_j
__device__ __forceinline__ void qmap8(const float* v, const float* phi, float* out) {
    float c[8];
    #pragma unroll
    for (int i = 0; i < 8; i++) c[i] = cosf(v[i] + phi[i]);
    float t = c[1];
    #pragma unroll
    for (int j = 2; j < 8; j++) t *= c[j];
    out[0] = t;
    float pref = c[0];
    #pragma unroll
    for (int i = 1; i < 8; i++) { pref *= c[i]; out[i] = pref; }
}
__device__ __forceinline__ void store_q8(__half* qp, const float* out) {
    __half2* q2 = (__half2*)qp;
    q2[0] = __floats2half2_rn(out[0], out[1]);
    q2[1] = __floats2half2_rn(out[2], out[3]);
    q2[2] = __floats2half2_rn(out[4], out[5]);
    q2[3] = __floats2half2_rn(out[6], out[7]);
}

// ---------------- 0. W2 -> fp16 copy ----------------
__global__ void w2cvt_kernel(const float* __restrict__ W2) {
    int i = blockIdx.x * blockDim.x + threadIdx.x;   // LL*FF*EE/4 threads
    float4 v = ((const float4*)W2)[i];
    __half2* dst = (__half2*)d_w2h;
    dst[2 * i]     = __floats2half2_rn(v.x, v.y);
    dst[2 * i + 1] = __floats2half2_rn(v.z, v.w);
}

// ---------------- 1. embedding + PE + layer-0 q (fused) ----------------
__global__ void embed_q_kernel(const int* __restrict__ tok, const float* __restrict__ emb,
                               const float* __restrict__ phi) {
    int g = blockIdx.x * blockDim.x + threadIdx.x;   // ROWS*32: (row, head)
    int row = g >> 5, h = g & 31;
    int s = row & (SS - 1);
    int base = row * EE + h * 8;
    const float4* er = (const float4*)(emb + (size_t)tok[row] * EE + h * 8);
    float4 e0 = er[0], e1 = er[1];
    float v[8] = {e0.x, e0.y, e0.z, e0.w, e1.x, e1.y, e1.z, e1.w};
    #pragma unroll
    for (int i = 0; i < 8; i++) {
        int e = h * 8 + i;
        float freq = expf((float)(e & ~1) * (-9.210340371976184f / 256.0f));
        float ang = (float)s * freq;
        v[i] += (e & 1) ? cosf(ang) : sinf(ang);
    }
    *(float4*)(d_x + base)     = make_float4(v[0], v[1], v[2], v[3]);
    *(float4*)(d_x + base + 4) = make_float4(v[4], v[5], v[6], v[7]);
    float out[8];
    qmap8(v, phi, out);
    store_q8(d_qh + base, out);
}

// ---------------- 2. fp16 tensor-core flash attention (Q = K = V = q) ----------------
// 8 warps / 64 Q rows; warp pair (w, w^1) shares 16 rows, each owns E half.
// Double-buffered cp.async K tiles.
#define KP 264                        // Ks row stride (halves)
#define SST 68                        // Sb row stride (fp32)
#define PP 72                         // Pb row stride (halves)
#define KS_BYTES (64 * KP * 2)        // 33792 per stage
#define SB_OFF (2 * KS_BYTES)         // 67584
#define SB_BYTES (8 * 16 * SST * 4)   // 34816
#define PB_OFF (SB_OFF + SB_BYTES)    // 102400
#define ATT_SMEM (PB_OFF + 8 * 16 * PP * 2)   // 120832

__global__ __launch_bounds__(256, 1) void attn_kernel() {
    extern __shared__ char smc[];
    float* Sb = (float*)(smc + SB_OFF);
    __half* Pb = (__half*)(smc + PB_OFF);
    const unsigned ks_s = (unsigned)__cvta_generic_to_shared(smc);

    const int tid = threadIdx.x;
    const int w = tid >> 5, lane = tid & 31;
    const int qt = lane >> 2, tq = lane & 3;
    const int eh = w & 1;
    const int b = blockIdx.y;
    const int row0 = blockIdx.x * 64 + (w >> 1) * 16;
    const __half* qbb = d_qh + (size_t)b * SS * EE;
    const float SCALE = 0.35355339059327373f;   // 1/sqrt(8)

    // Q A-fragments (fp16x2 regs), 8 ksteps covering this warp's E half
    unsigned qa[8][4];
    {
        const __half* p0 = qbb + (size_t)(row0 + qt) * EE + eh * 128 + 2 * tq;
        #pragma unroll
        for (int k = 0; k < 8; k++) {
            qa[k][0] = *(const unsigned*)(p0 + 16 * k);
            qa[k][1] = *(const unsigned*)(p0 + 8 * EE + 16 * k);
            qa[k][2] = *(const unsigned*)(p0 + 16 * k + 8);
            qa[k][3] = *(const unsigned*)(p0 + 8 * EE + 16 * k + 8);
        }
    }
    float o[16][4];
    #pragma unroll
    for (int n = 0; n < 16; n++) { o[n][0] = o[n][1] = o[n][2] = o[n][3] = 0.f; }
    float m0 = -1e30f, m1 = -1e30f, l0 = 0.f, l1 = 0.f;

    float* Sw = Sb + w * 16 * SST;
    float* Sp = Sb + (w ^ 1) * 16 * SST;
    __half* Pw = Pb + w * 16 * PP;
    const unsigned pw_s = (unsigned)__cvta_generic_to_shared(Pw);

    const int l7 = lane & 7, l3 = lane >> 3;
    // ldsm bases (byte offsets within a K stage)
    const unsigned qk_off = 2u * (unsigned)(l7 * KP + eh * 128 + 8 * l3);
    const unsigned pv_off = 2u * (unsigned)((l7 + 8 * (l3 & 1)) * KP + eh * 128 + 8 * (l3 >> 1));
    const unsigned pa_addr = pw_s + 2u * (unsigned)((l7 + 8 * (l3 & 1)) * PP + 8 * (l3 >> 1));

    // prologue: prefetch tile 0 into stage 0
    {
        const uint4* src = (const uint4*)qbb;
        #pragma unroll
        for (int p = 0; p < 8; p++) {
            int idx = p * 256 + tid;
            cpasync16(ks_s + 2u * (unsigned)((idx >> 5) * KP + (idx & 31) * 8), src + idx);
        }
        CP_COMMIT();
    }

    for (int kt = 0; kt < SS / 64; kt++) {
        const int cur = kt & 1;
        const unsigned ks_cur = ks_s + (unsigned)(cur * KS_BYTES);
        __syncthreads();                       // all warps done reading stage cur^1
        if (kt + 1 < SS / 64) {
            const uint4* src = (const uint4*)(qbb + (size_t)(kt + 1) * 64 * EE);
            const unsigned dst = ks_s + (unsigned)((cur ^ 1) * KS_BYTES);
            #pragma unroll
            for (int p = 0; p < 8; p++) {
                int idx = p * 256 + tid;
                cpasync16(dst + 2u * (unsigned)((idx >> 5) * KP + (idx & 31) * 8), src + idx);
            }
        }
        CP_COMMIT();
        CP_WAIT1();                            // tile kt resident
        __syncthreads();

        // S_half = Q_half @ K_half^T  (16x64)
        float sc[8][4];
        #pragma unroll
        for (int n = 0; n < 8; n++) { sc[n][0] = sc[n][1] = sc[n][2] = sc[n][3] = 0.f; }
        #pragma unroll
        for (int n = 0; n < 8; n++) {
            unsigned base = ks_cur + qk_off + (unsigned)(n * 8 * KP * 2);
            #pragma unroll
            for (int kk = 0; kk < 4; kk++) {
                unsigned b0, b1, b2, b3;
                ldsm4(b0, b1, b2, b3, base + kk * 64);
                MMA_F16(sc[n], qa[2*kk][0], qa[2*kk][1], qa[2*kk][2], qa[2*kk][3], b0, b1);
                MMA_F16(sc[n], qa[2*kk+1][0], qa[2*kk+1][1], qa[2*kk+1][2], qa[2*kk+1][3], b2, b3);
            }
        }

        // exchange halves with partner warp, apply scale
        #pragma unroll
        for (int n = 0; n < 8; n++) {
            *(float2*)(Sw + qt * SST + n * 8 + 2 * tq)       = make_float2(sc[n][0], sc[n][1]);
            *(float2*)(Sw + (qt + 8) * SST + n * 8 + 2 * tq) = make_float2(sc[n][2], sc[n][3]);
        }
        __syncthreads();
        #pragma unroll
        for (int n = 0; n < 8; n++) {
            float2 p0 = *(const float2*)(Sp + qt * SST + n * 8 + 2 * tq);
            float2 p1 = *(const float2*)(Sp + (qt + 8) * SST + n * 8 + 2 * tq);
            sc[n][0] = (sc[n][0] + p0.x) * SCALE;
            sc[n][1] = (sc[n][1] + p0.y) * SCALE;
            sc[n][2] = (sc[n][2] + p1.x) * SCALE;
            sc[n][3] = (sc[n][3] + p1.y) * SCALE;
        }

        // online softmax
        float mx0 = sc[0][0], mx1 = sc[0][2];
        #pragma unroll
        for (int n = 0; n < 8; n++) {
            mx0 = fmaxf(mx0, fmaxf(sc[n][0], sc[n][1]));
            mx1 = fmaxf(mx1, fmaxf(sc[n][2], sc[n][3]));
        }
        mx0 = fmaxf(mx0, __shfl_xor_sync(0xffffffffu, mx0, 1));
        mx0 = fmaxf(mx0, __shfl_xor_sync(0xffffffffu, mx0, 2));
        mx1 = fmaxf(mx1, __shfl_xor_sync(0xffffffffu, mx1, 1));
        mx1 = fmaxf(mx1, __shfl_xor_sync(0xffffffffu, mx1, 2));
        float nm0 = fmaxf(m0, mx0), nm1 = fmaxf(m1, mx1);
        float c0 = __expf(m0 - nm0), c1 = __expf(m1 - nm1);
        m0 = nm0; m1 = nm1; l0 *= c0; l1 *= c1;
        #pragma unroll
        for (int n = 0; n < 16; n++) {
            o[n][0] *= c0; o[n][1] *= c0; o[n][2] *= c1; o[n][3] *= c1;
        }
        // P = exp(S - m), fp16-rounded (l accumulated from the ROUNDED values)
        float s0 = 0.f, s1 = 0.f;
        #pragma unroll
        for (int n = 0; n < 8; n++) {
            __half2 h0 = __floats2half2_rn(__expf(sc[n][0] - m0), __expf(sc[n][1] - m0));
            __half2 h1 = __floats2half2_rn(__expf(sc[n][2] - m1), __expf(sc[n][3] - m1));
            *(__half2*)(Pw + qt * PP + n * 8 + 2 * tq)       = h0;
            *(__half2*)(Pw + (qt + 8) * PP + n * 8 + 2 * tq) = h1;
            s0 += __low2float(h0) + __high2float(h0);
            s1 += __low2float(h1) + __high2float(h1);
        }
        s0 += __shfl_xor_sync(0xffffffffu, s0, 1);
        s0 += __shfl_xor_sync(0xffffffffu, s0, 2);
        s1 += __shfl_xor_sync(0xffffffffu, s1, 1);
        s1 += __shfl_xor_sync(0xffffffffu, s1, 2);
        l0 += s0; l1 += s1;
        __syncwarp();

        // P A-fragments via ldmatrix
        unsigned pa[4][4];
        #pragma unroll
        for (int k = 0; k < 4; k++)
            ldsm4(pa[k][0], pa[k][1], pa[k][2], pa[k][3], pa_addr + (unsigned)(k * 32));

        // O_half += P @ V_half  (V = same K tile, ldmatrix.trans)
        #pragma unroll
        for (int np = 0; np < 8; np++) {
            unsigned base = ks_cur + pv_off + (unsigned)(np * 32);
            #pragma unroll
            for (int k = 0; k < 4; k++) {
                unsigned b0, b1, b2, b3;
                ldsm4t(b0, b1, b2, b3, base + (unsigned)(k * 16 * KP * 2));
                MMA_F16(o[2*np],   pa[k][0], pa[k][1], pa[k][2], pa[k][3], b0, b1);
                MMA_F16(o[2*np+1], pa[k][0], pa[k][1], pa[k][2], pa[k][3], b2, b3);
            }
        }
    }

    // write O
    float i0 = 1.f / l0, i1 = 1.f / l1;
    float* outp = d_a + ((size_t)b * SS + row0) * EE;
    #pragma unroll
    for (int n = 0; n < 16; n++) {
        int col = eh * 128 + n * 8 + 2 * tq;
        *(float2*)(outp + (size_t)qt * EE + col)       = make_float2(o[n][0] * i0, o[n][1] * i0);
        *(float2*)(outp + (size_t)(qt + 8) * EE + col) = make_float2(o[n][2] * i1, o[n][3] * i1);
    }
}

// ---------------- 3. x = LayerNorm(x + a), optional fused q for next layer ----------------
__global__ void addln_kernel(const float* __restrict__ gam, const float* __restrict__ bet,
                             const float* __restrict__ phi) {
    int warp = threadIdx.x >> 5, lane = threadIdx.x & 31;
    int row = blockIdx.x * 8 + warp;
    int base = row * EE + lane * 8;
    float4 x0 = *(float4*)(d_x + base), x1 = *(float4*)(d_x + base + 4);
    float4 f0 = *(const float4*)(d_a + base), f1 = *(const float4*)(d_a + base + 4);
    float v[8] = {x0.x + f0.x, x0.y + f0.y, x0.z + f0.z, x0.w + f0.w,
                  x1.x + f1.x, x1.y + f1.y, x1.z + f1.z, x1.w + f1.w};
    float sum = 0.f, sq = 0.f;
    #pragma unroll
    for (int i = 0; i < 8; i++) { sum += v[i]; sq += v[i] * v[i]; }
    #pragma unroll
    for (int mask = 16; mask >= 1; mask >>= 1) {
        sum += __shfl_xor_sync(0xffffffffu, sum, mask);
        sq  += __shfl_xor_sync(0xffffffffu, sq, mask);
    }
    float mean = sum * (1.f / EE);
    float var = sq * (1.f / EE) - mean * mean;
    float inv = rsqrtf(var + 1e-5f);
    float4 g0 = *(const float4*)(gam + lane * 8), g1v = *(const float4*)(gam + lane * 8 + 4);
    float4 b0 = *(const float4*)(bet + lane * 8), b1v = *(const float4*)(bet + lane * 8 + 4);
    float gv[8] = {g0.x, g0.y, g0.z, g0.w, g1v.x, g1v.y, g1v.z, g1v.w};
    float bv[8] = {b0.x, b0.y, b0.z, b0.w, b1v.x, b1v.y, b1v.z, b1v.w};
    #pragma unroll
    for (int i = 0; i < 8; i++) v[i] = (v[i] - mean) * inv * gv[i] + bv[i];
    *(float4*)(d_x + base)     = make_float4(v[0], v[1], v[2], v[3]);
    *(float4*)(d_x + base + 4) = make_float4(v[4], v[5], v[6], v[7]);
    if (phi) {
        float out[8];
        qmap8(v, phi, out);
        store_q8(d_qh + base, out);
    }
}

// ---------------- 4. fused FFN on tensor cores (fp16 mma, fp32 accum) ----------------
// CTA: 64 rows x 256 cols; warp = 32 rows x 64 cols
// NOTE: layer index passed, W2h resolved from d_w2h in DEVICE code (device symbol
// addresses are invalid when computed host-side).
#define HSP 40    // hs row stride (halves)
#define WSP 264   // ws row stride (halves)
__global__ __launch_bounds__(256, 2) void ffn_kernel(const float* __restrict__ theta,
                                                     const float* __restrict__ W1,
                                                     const float* __restrict__ b1,
                                                     int layer,
                                                     const float* __restrict__ b2) {
    __shared__ float qm[64][9];
    __shared__ float w1s[8][33];
    __shared__ __half hs[64][HSP];
    __shared__ __half ws[32][WSP];
    __shared__ float b1s[FF];
    __shared__ float b2s[256];
    const __half* __restrict__ W2h = d_w2h + (size_t)layer * FF * EE;
    const int t = threadIdx.x, w = t >> 5, lane = t & 31;
    const int qt = lane >> 2, tq = lane & 3;
    const int l7 = lane & 7, l3 = lane >> 3;
    const int wm = w >> 2, wn = w & 3;
    const int rowBase = blockIdx.x * 64;
    const unsigned hs_s = (unsigned)__cvta_generic_to_shared(hs);
    const unsigned ws_s = (unsigned)__cvta_generic_to_shared(ws);

    b2s[t] = b2[t];
    #pragma unroll
    for (int p = 0; p < 4; p++) b1s[t + p * 256] = b1[t + p * 256];
    #pragma unroll
    for (int i = 0; i < 2; i++) {
        int idx = t * 2 + i;
        int r = idx >> 3, j = idx & 7;
        qm[r][j] = cosf(d_x[(size_t)(rowBase + r) * EE + j]) * cosf(theta[j]);
    }

    float c[2][8][4];
    #pragma unroll
    for (int mt = 0; mt < 2; mt++)
        #pragma unroll
        for (int nt = 0; nt < 8; nt++)
            c[mt][nt][0] = c[mt][nt][1] = c[mt][nt][2] = c[mt][nt][3] = 0.f;

    for (int kt = 0; kt < FF / 32; kt++) {
        int k0g = kt * 32;
        __syncthreads();
        w1s[t >> 5][t & 31] = W1[(t >> 5) * FF + k0g + (t & 31)];
        {   // W2 fp16 tile 32x256
            const uint4* w4 = (const uint4*)(W2h + (size_t)k0g * EE);
            #pragma unroll
            for (int p = 0; p < 4; p++) {
                int idx = p * 256 + t;
                *(uint4*)(&ws[idx >> 5][(idx & 31) * 8]) = w4[idx];
            }
        }
        __syncthreads();
        {   // hidden tile 64x32 via fused ffn1 (fp32 math -> fp16 store)
            int r = t & 63, cg = (t >> 6) * 8;
            #pragma unroll
            for (int i = 0; i < 8; i++) {
                int cc = cg + i;
                float h = b1s[k0g + cc];
                #pragma unroll
                for (int j = 0; j < 8; j++) h += qm[r][j] * w1s[j][cc];
                hs[r][cc] = __float2half(fmaxf(h, 0.f));
            }
        }
        __syncthreads();
        #pragma unroll
        for (int ks = 0; ks < 2; ks++) {
            unsigned a[2][4];
            #pragma unroll
            for (int mt = 0; mt < 2; mt++) {
                int mrow = wm * 32 + mt * 16;
                unsigned addr = hs_s + 2u * (unsigned)((mrow + l7 + 8 * (l3 & 1)) * HSP +
                                                       ks * 16 + 8 * (l3 >> 1));
                ldsm4(a[mt][0], a[mt][1], a[mt][2], a[mt][3], addr);
            }
            #pragma unroll
            for (int ng = 0; ng < 4; ng++) {
                int n0 = wn * 64 + ng * 16;
                unsigned baddr = ws_s + 2u * (unsigned)((ks * 16 + l7 + 8 * (l3 & 1)) * WSP +
                                                        n0 + 8 * (l3 >> 1));
                unsigned b0, b1r, b2r, b3;
                ldsm4t(b0, b1r, b2r, b3, baddr);
                MMA_F16(c[0][2*ng],   a[0][0], a[0][1], a[0][2], a[0][3], b0, b1r);
                MMA_F16(c[0][2*ng+1], a[0][0], a[0][1], a[0][2], a[0][3], b2r, b3);
                MMA_F16(c[1][2*ng],   a[1][0], a[1][1], a[1][2], a[1][3], b0, b1r);
                MMA_F16(c[1][2*ng+1], a[1][0], a[1][1], a[1][2], a[1][3], b2r, b3);
            }
        }
    }
    #pragma unroll
    for (int mt = 0; mt < 2; mt++) {
        int gr = rowBase + wm * 32 + mt * 16;
        #pragma unroll
        for (int nt = 0; nt < 8; nt++) {
            int col = wn * 64 + nt * 8 + 2 * tq;
            float bb0 = b2s[col], bb1 = b2s[col + 1];
            *(float2*)(d_a + (size_t)(gr + qt) * EE + col) =
                make_float2(c[mt][nt][0] + bb0, c[mt][nt][1] + bb1);
            *(float2*)(d_a + (size_t)(gr + qt + 8) * EE + col) =
                make_float2(c[mt][nt][2] + bb0, c[mt][nt][3] + bb1);
        }
    }
}

// ---------------- 5. mean over S + classifier head ----------------
__global__ void head_kernel(const float* __restrict__ Wc, const float* __restrict__ bc,
                            float* __restrict__ out) {
    __shared__ float sm[1024];
    __shared__ float mean[EE];
    int b = blockIdx.x;
    int e = threadIdx.x & 255;
    int chunk = threadIdx.x >> 8;
    float s = 0.f;
    for (int i = 0; i < SS / 4; i++) {
        int srow = chunk * (SS / 4) + i;
        s += d_x[((size_t)b * SS + srow) * EE + e];
    }
    sm[threadIdx.x] = s;
    __syncthreads();
    if (threadIdx.x < 256) {
        float tot = sm[e] + sm[e + 256] + sm[e + 512] + sm[e + 768];
        mean[e] = tot * (1.f / SS);
    }
    __syncthreads();
    if (threadIdx.x < NC) {
        float acc = bc[threadIdx.x];
        for (int ee = 0; ee < EE; ee++)
            acc += mean[ee] * Wc[ee * NC + threadIdx.x];
        out[b * NC + threadIdx.x] = acc;
    }
}

// ---------------- launch ----------------
extern "C" void kernel_launch(void* const* d_in, const int* in_sizes, int n_in,
                              void* d_out, int out_size) {
    const int*   tok   = (const int*)d_in[0];
    const float* emb   = (const float*)d_in[1];
    const float* phi   = (const float*)d_in[2];
    const float* theta = (const float*)d_in[3];
    const float* W1    = (const float*)d_in[4];
    const float* b1    = (const float*)d_in[5];
    const float* W2    = (const float*)d_in[6];
    const float* b2    = (const float*)d_in[7];
    const float* g1    = (const float*)d_in[8];
    const float* be1   = (const float*)d_in[9];
    const float* g2    = (const float*)d_in[10];
    const float* be2   = (const float*)d_in[11];
    const float* Wc    = (const float*)d_in[12];
    const float* bc    = (const float*)d_in[13];
    float* out = (float*)d_out;

    cudaFuncSetAttribute(attn_kernel, cudaFuncAttributeMaxDynamicSharedMemorySize, ATT_SMEM);

    w2cvt_kernel<<<LL * FF * EE / 4 / 256, 256>>>(W2);
    embed_q_kernel<<<ROWS * 32 / 256, 256>>>(tok, emb, phi);
    for (int l = 0; l < LL; l++) {
        attn_kernel<<<dim3(SS / 64, BB), 256, ATT_SMEM>>>();
        addln_kernel<<<ROWS / 8, 256>>>(g1 + l * EE, be1 + l * EE, nullptr);
        ffn_kernel<<<ROWS / 64, 256>>>(theta + l * NQ, W1 + (size_t)l * NQ * FF,
                                       b1 + l * FF, l, b2 + l * EE);
        addln_kernel<<<ROWS / 8, 256>>>(g2 + l * EE, be2 + l * EE,
                                        (l < LL - 1) ? (phi + (l + 1) * NQ) : nullptr);
    }
    head_kernel<<<BB, 1024>>>(Wc, bc, out);
}

// round 8
// speedup vs baseline: 7.9722x; 1.0845x over previous
#include <cuda_runtime.h>
#include <cuda_fp16.h>
#include <math.h>

#define BB 8
#define SS 2048
#define EE 256
#define LL 4
#define FF 1024
#define NQ 8
#define NC 10
#define ROWS (BB*SS)   // 16384

// ---------------- scratch (static device arrays; no allocation) ----------------
__device__ float d_x[ROWS*EE];            // activations  (16 MB)
__device__ __half d_qh[ROWS*EE];          // quantum q, fp16 (8 MB)
__device__ float d_a[ROWS*EE];            // ffn out (16 MB)
__device__ __half d_w2h[LL*FF*EE];        // fp16 copy of W2 (4 MB)

#define MMA_F16(d, a0, a1, a2, a3, b0, b1)                                    \
    asm volatile(                                                             \
        "mma.sync.aligned.m16n8k16.row.col.f32.f16.f16.f32 "                  \
        "{%0,%1,%2,%3}, {%4,%5,%6,%7}, {%8,%9}, {%0,%1,%2,%3};"               \
        : "+f"(d[0]), "+f"(d[1]), "+f"(d[2]), "+f"(d[3])                      \
        : "r"(a0), "r"(a1), "r"(a2), "r"(a3), "r"(b0), "r"(b1))

__device__ __forceinline__ void ldsm4(unsigned& r0, unsigned& r1, unsigned& r2,
                                      unsigned& r3, unsigned a) {
    asm volatile("ldmatrix.sync.aligned.m8n8.x4.shared.b16 {%0,%1,%2,%3}, [%4];"
                 : "=r"(r0), "=r"(r1), "=r"(r2), "=r"(r3) : "r"(a));
}
__device__ __forceinline__ void ldsm4t(unsigned& r0, unsigned& r1, unsigned& r2,
                                       unsigned& r3, unsigned a) {
    asm volatile("ldmatrix.sync.aligned.m8n8.x4.trans.shared.b16 {%0,%1,%2,%3}, [%4];"
                 : "=r"(r0), "=r"(r1), "=r"(r2), "=r"(r3) : "r"(a));
}
__device__ __forceinline__ void cpasync16(unsigned dst, const void* src) {
    asm volatile("cp.async.cg.shared.global [%0], [%1], 16;" :: "r"(dst), "l"(src));
}
#define CP_COMMIT() asm volatile("cp.async.commit_group;" ::: "memory")
#define CP_WAIT1()  asm volatile("cp.async.wait_group 1;" ::: "memory")

// q-map: c_j = cos(v_j + phi_j); q_0 = prod_{j>=1} c_j; q_i = prod_{j<=i} c_j
__device__ __forceinline__ void qmap8(const float* v, const float* phi, float* out) {
    float c[8];
    #pragma unroll
    for (int i = 0; i < 8; i++) c[i] = cosf(v[i] + phi[i]);
    float t = c[1];
    #pragma unroll
    for (int j = 2; j < 8; j++) t *= c[j];
    out[0] = t;
    float pref = c[0];
    #pragma unroll
    for (int i = 1; i < 8; i++) { pref *= c[i]; out[i] = pref; }
}
__device__ __forceinline__ void store_q8(__half* qp, const float* out) {
    __half2* q2 = (__half2*)qp;
    q2[0] = __floats2half2_rn(out[0], out[1]);
    q2[1] = __floats2half2_rn(out[2], out[3]);
    q2[2] = __floats2half2_rn(out[4], out[5]);
    q2[3] = __floats2half2_rn(out[6], out[7]);
}

// ---------------- 0. W2 -> fp16 copy ----------------
__global__ void w2cvt_kernel(const float* __restrict__ W2) {
    int i = blockIdx.x * blockDim.x + threadIdx.x;
    float4 v = ((const float4*)W2)[i];
    __half2* dst = (__half2*)d_w2h;
    dst[2 * i]     = __floats2half2_rn(v.x, v.y);
    dst[2 * i + 1] = __floats2half2_rn(v.z, v.w);
}

// ---------------- 1. embedding + PE + layer-0 q (fused) ----------------
__global__ void embed_q_kernel(const int* __restrict__ tok, const float* __restrict__ emb,
                               const float* __restrict__ phi) {
    int g = blockIdx.x * blockDim.x + threadIdx.x;   // ROWS*32: (row, head)
    int row = g >> 5, h = g & 31;
    int s = row & (SS - 1);
    int base = row * EE + h * 8;
    const float4* er = (const float4*)(emb + (size_t)tok[row] * EE + h * 8);
    float4 e0 = er[0], e1 = er[1];
    float v[8] = {e0.x, e0.y, e0.z, e0.w, e1.x, e1.y, e1.z, e1.w};
    #pragma unroll
    for (int i = 0; i < 8; i++) {
        int e = h * 8 + i;
        float freq = expf((float)(e & ~1) * (-9.210340371976184f / 256.0f));
        float ang = (float)s * freq;
        v[i] += (e & 1) ? cosf(ang) : sinf(ang);
    }
    *(float4*)(d_x + base)     = make_float4(v[0], v[1], v[2], v[3]);
    *(float4*)(d_x + base + 4) = make_float4(v[4], v[5], v[6], v[7]);
    float out[8];
    qmap8(v, phi, out);
    store_q8(d_qh + base, out);
}

// ---------------- 2. fp16 flash attention + fused residual LayerNorm ----------------
// 8 warps / 64 Q rows; warp pair (w, w^1) shares 16 rows, each owns an E half.
// 3-stage cp.async K ring; P stays in registers (C-frag == A-frag layout);
// epilogue does x = LN(x + O) and writes d_x directly.
#define NSTG 3
#define KP 264                        // Ks row stride (halves)
#define SST 68                        // Sb row stride (fp32)
#define KS_BYTES (64 * KP * 2)        // 33792 per stage
#define SB_OFF (NSTG * KS_BYTES)      // 101376
#define SB_BYTES (8 * 16 * SST * 4)   // 34816
#define RED_OFF (SB_OFF + SB_BYTES)   // 136192  (float2 red[4][16][2] = 1024B)
#define GS_OFF (RED_OFF + 1024)
#define BS_OFF (GS_OFF + 1024)
#define ATT_SMEM (BS_OFF + 1024)      // 139264

__global__ __launch_bounds__(256, 1) void attn_kernel(const float* __restrict__ gam,
                                                      const float* __restrict__ bet) {
    extern __shared__ char smc[];
    float* Sb = (float*)(smc + SB_OFF);
    float2* red = (float2*)(smc + RED_OFF);
    float* gs = (float*)(smc + GS_OFF);
    float* bs = (float*)(smc + BS_OFF);
    const unsigned ks_s = (unsigned)__cvta_generic_to_shared(smc);

    const int tid = threadIdx.x;
    const int w = tid >> 5, lane = tid & 31;
    const int qt = lane >> 2, tq = lane & 3;
    const int eh = w & 1;
    const int b = blockIdx.y;
    const int row0 = blockIdx.x * 64 + (w >> 1) * 16;
    const __half* qbb = d_qh + (size_t)b * SS * EE;
    const float C = 0.51006977f;   // log2(e)/sqrt(8)

    gs[tid] = gam[tid];
    bs[tid] = bet[tid];

    // Q A-fragments (fp16x2 regs), 8 ksteps over this warp's E half
    unsigned qa[8][4];
    {
        const __half* p0 = qbb + (size_t)(row0 + qt) * EE + eh * 128 + 2 * tq;
        #pragma unroll
        for (int k = 0; k < 8; k++) {
            qa[k][0] = *(const unsigned*)(p0 + 16 * k);
            qa[k][1] = *(const unsigned*)(p0 + 8 * EE + 16 * k);
            qa[k][2] = *(const unsigned*)(p0 + 16 * k + 8);
            qa[k][3] = *(const unsigned*)(p0 + 8 * EE + 16 * k + 8);
        }
    }
    float o[16][4];
    #pragma unroll
    for (int n = 0; n < 16; n++) { o[n][0] = o[n][1] = o[n][2] = o[n][3] = 0.f; }
    float m0 = -1e30f, m1 = -1e30f, l0 = 0.f, l1 = 0.f;

    float* Sw = Sb + w * 16 * SST;
    float* Sp = Sb + (w ^ 1) * 16 * SST;

    const int l7 = lane & 7, l3 = lane >> 3;
    const unsigned qk_off = 2u * (unsigned)(l7 * KP + eh * 128 + 8 * l3);
    const unsigned pv_off = 2u * (unsigned)((l7 + 8 * (l3 & 1)) * KP + eh * 128 + 8 * (l3 >> 1));

    // prologue: prefetch tiles 0,1 into stages 0,1
    #pragma unroll
    for (int t = 0; t < 2; t++) {
        const uint4* src = (const uint4*)(qbb + (size_t)t * 64 * EE);
        const unsigned dst = ks_s + (unsigned)(t * KS_BYTES);
        #pragma unroll
        for (int p = 0; p < 8; p++) {
            int idx = p * 256 + tid;
            cpasync16(dst + 2u * (unsigned)((idx >> 5) * KP + (idx & 31) * 8), src + idx);
        }
        CP_COMMIT();
    }

    int cur = 0;
    for (int kt = 0; kt < SS / 64; kt++) {
        CP_WAIT1();                       // tile kt resident (kt+1 may be in flight)
        __syncthreads();                  // visible to all; prev-iter reads done

        // prefetch tile kt+2 into stage (cur+2)%3 (last read at iter kt-1, safe)
        if (kt + 2 < SS / 64) {
            int nxt = cur + 2; if (nxt >= NSTG) nxt -= NSTG;
            const uint4* src = (const uint4*)(qbb + (size_t)(kt + 2) * 64 * EE);
            const unsigned dst = ks_s + (unsigned)(nxt * KS_BYTES);
            #pragma unroll
            for (int p = 0; p < 8; p++) {
                int idx = p * 256 + tid;
                cpasync16(dst + 2u * (unsigned)((idx >> 5) * KP + (idx & 31) * 8), src + idx);
            }
        }
        CP_COMMIT();                      // commit (possibly empty) keeps group count

        const unsigned ks_cur = ks_s + (unsigned)(cur * KS_BYTES);

        // S_half = Q_half @ K_half^T  (16x64), raw units
        float sc[8][4];
        #pragma unroll
        for (int n = 0; n < 8; n++) { sc[n][0] = sc[n][1] = sc[n][2] = sc[n][3] = 0.f; }
        #pragma unroll
        for (int n = 0; n < 8; n++) {
            unsigned base = ks_cur + qk_off + (unsigned)(n * 8 * KP * 2);
            #pragma unroll
            for (int kk = 0; kk < 4; kk++) {
                unsigned b0, b1, b2, b3;
                ldsm4(b0, b1, b2, b3, base + kk * 64);
                MMA_F16(sc[n], qa[2*kk][0], qa[2*kk][1], qa[2*kk][2], qa[2*kk][3], b0, b1);
                MMA_F16(sc[n], qa[2*kk+1][0], qa[2*kk+1][1], qa[2*kk+1][2], qa[2*kk+1][3], b2, b3);
            }
        }

        // exchange halves with partner warp (raw; scale folded into exp2)
        #pragma unroll
        for (int n = 0; n < 8; n++) {
            *(float2*)(Sw + qt * SST + n * 8 + 2 * tq)       = make_float2(sc[n][0], sc[n][1]);
            *(float2*)(Sw + (qt + 8) * SST + n * 8 + 2 * tq) = make_float2(sc[n][2], sc[n][3]);
        }
        __syncthreads();
        #pragma unroll
        for (int n = 0; n < 8; n++) {
            float2 p0 = *(const float2*)(Sp + qt * SST + n * 8 + 2 * tq);
            float2 p1 = *(const float2*)(Sp + (qt + 8) * SST + n * 8 + 2 * tq);
            sc[n][0] += p0.x; sc[n][1] += p0.y;
            sc[n][2] += p1.x; sc[n][3] += p1.y;
        }

        // online softmax (raw-unit max; exp2 with folded scale)
        float mx0 = sc[0][0], mx1 = sc[0][2];
        #pragma unroll
        for (int n = 0; n < 8; n++) {
            mx0 = fmaxf(mx0, fmaxf(sc[n][0], sc[n][1]));
            mx1 = fmaxf(mx1, fmaxf(sc[n][2], sc[n][3]));
        }
        mx0 = fmaxf(mx0, __shfl_xor_sync(0xffffffffu, mx0, 1));
        mx0 = fmaxf(mx0, __shfl_xor_sync(0xffffffffu, mx0, 2));
        mx1 = fmaxf(mx1, __shfl_xor_sync(0xffffffffu, mx1, 1));
        mx1 = fmaxf(mx1, __shfl_xor_sync(0xffffffffu, mx1, 2));
        float nm0 = fmaxf(m0, mx0), nm1 = fmaxf(m1, mx1);
        float c0 = exp2f((m0 - nm0) * C), c1 = exp2f((m1 - nm1) * C);
        m0 = nm0; m1 = nm1; l0 *= c0; l1 *= c1;
        #pragma unroll
        for (int n = 0; n < 16; n++) {
            o[n][0] *= c0; o[n][1] *= c0; o[n][2] *= c1; o[n][3] *= c1;
        }

        // P stays in registers: C-frag of S packs directly into A-frag of PV.
        // pa[kk]: a0=P[qt][16kk+2tq..], a1=P[qt+8][..], a2/a3 = +8 key cols.
        unsigned pa[4][4];
        float s0 = 0.f, s1 = 0.f;
        #pragma unroll
        for (int kk = 0; kk < 4; kk++) {
            int n0 = 2 * kk, n1 = 2 * kk + 1;
            __half2 h;
            h = __floats2half2_rn(exp2f((sc[n0][0] - m0) * C), exp2f((sc[n0][1] - m0) * C));
            pa[kk][0] = *(unsigned*)&h; s0 += __low2float(h) + __high2float(h);
            h = __floats2half2_rn(exp2f((sc[n0][2] - m1) * C), exp2f((sc[n0][3] - m1) * C));
            pa[kk][1] = *(unsigned*)&h; s1 += __low2float(h) + __high2float(h);
            h = __floats2half2_rn(exp2f((sc[n1][0] - m0) * C), exp2f((sc[n1][1] - m0) * C));
            pa[kk][2] = *(unsigned*)&h; s0 += __low2float(h) + __high2float(h);
            h = __floats2half2_rn(exp2f((sc[n1][2] - m1) * C), exp2f((sc[n1][3] - m1) * C));
            pa[kk][3] = *(unsigned*)&h; s1 += __low2float(h) + __high2float(h);
        }
        s0 += __shfl_xor_sync(0xffffffffu, s0, 1);
        s0 += __shfl_xor_sync(0xffffffffu, s0, 2);
        s1 += __shfl_xor_sync(0xffffffffu, s1, 1);
        s1 += __shfl_xor_sync(0xffffffffu, s1, 2);
        l0 += s0; l1 += s1;

        // O_half += P @ V_half  (V = same K tile, ldmatrix.trans)
        #pragma unroll
        for (int np = 0; np < 8; np++) {
            unsigned base = ks_cur + pv_off + (unsigned)(np * 32);
            #pragma unroll
            for (int kk = 0; kk < 4; kk++) {
                unsigned b0, b1, b2, b3;
                ldsm4t(b0, b1, b2, b3, base + (unsigned)(kk * 16 * KP * 2));
                MMA_F16(o[2*np],   pa[kk][0], pa[kk][1], pa[kk][2], pa[kk][3], b0, b1);
                MMA_F16(o[2*np+1], pa[kk][0], pa[kk][1], pa[kk][2], pa[kk][3], b2, b3);
            }
        }
        cur = (cur + 1 == NSTG) ? 0 : cur + 1;
    }

    // ---- fused epilogue: x = LayerNorm(x + O) written straight to d_x ----
    // residual-add folded IN PLACE into o[] (keeps register count down)
    float i0 = 1.f / l0, i1 = 1.f / l1;
    float* xr0 = d_x + ((size_t)b * SS + row0 + qt) * EE;
    float* xr1 = d_x + ((size_t)b * SS + row0 + qt + 8) * EE;
    float sum0 = 0.f, sq0 = 0.f, sum1 = 0.f, sq1 = 0.f;
    #pragma unroll
    for (int n = 0; n < 16; n++) {
        int col = eh * 128 + n * 8 + 2 * tq;
        float2 x0 = *(const float2*)(xr0 + col);
        float2 x1 = *(const float2*)(xr1 + col);
        o[n][0] = o[n][0] * i0 + x0.x;  o[n][1] = o[n][1] * i0 + x0.y;
        o[n][2] = o[n][2] * i1 + x1.x;  o[n][3] = o[n][3] * i1 + x1.y;
        sum0 += o[n][0] + o[n][1]; sq0 += o[n][0] * o[n][0] + o[n][1] * o[n][1];
        sum1 += o[n][2] + o[n][3]; sq1 += o[n][2] * o[n][2] + o[n][3] * o[n][3];
    }
    #pragma unroll
    for (int mask = 1; mask <= 2; mask <<= 1) {
        sum0 += __shfl_xor_sync(0xffffffffu, sum0, mask);
        sq0  += __shfl_xor_sync(0xffffffffu, sq0, mask);
        sum1 += __shfl_xor_sync(0xffffffffu, sum1, mask);
        sq1  += __shfl_xor_sync(0xffffffffu, sq1, mask);
    }
    int pair = w >> 1;
    if (tq == 0) {
        red[(pair * 16 + qt) * 2 + eh]     = make_float2(sum0, sq0);
        red[(pair * 16 + qt + 8) * 2 + eh] = make_float2(sum1, sq1);
    }
    __syncthreads();
    float2 ra = red[(pair * 16 + qt) * 2 + 0], rb = red[(pair * 16 + qt) * 2 + 1];
    float mean0 = (ra.x + rb.x) * (1.f / EE);
    float var0 = (ra.y + rb.y) * (1.f / EE) - mean0 * mean0;
    float rv0 = rsqrtf(var0 + 1e-5f);
    float2 rc = red[(pair * 16 + qt + 8) * 2 + 0], rd = red[(pair * 16 + qt + 8) * 2 + 1];
    float mean1 = (rc.x + rd.x) * (1.f / EE);
    float var1 = (rc.y + rd.y) * (1.f / EE) - mean1 * mean1;
    float rv1 = rsqrtf(var1 + 1e-5f);
    #pragma unroll
    for (int n = 0; n < 16; n++) {
        int col = eh * 128 + n * 8 + 2 * tq;
        float2 gv = *(const float2*)(gs + col);
        float2 bv = *(const float2*)(bs + col);
        *(float2*)(xr0 + col) = make_float2((o[n][0] - mean0) * rv0 * gv.x + bv.x,
                                            (o[n][1] - mean0) * rv0 * gv.y + bv.y);
        *(float2*)(xr1 + col) = make_float2((o[n][2] - mean1) * rv1 * gv.x + bv.x,
                                            (o[n][3] - mean1) * rv1 * gv.y + bv.y);
    }
}

// ---------------- 3. x = LayerNorm(x + a), optional fused q for next layer ----------------
__global__ void addln_kernel(const float* __restrict__ gam, const float* __restrict__ bet,
                             const float* __restrict__ phi) {
    int warp = threadIdx.x >> 5, lane = threadIdx.x & 31;
    int row = blockIdx.x * 8 + warp;
    int base = row * EE + lane * 8;
    float4 x0 = *(float4*)(d_x + base), x1 = *(float4*)(d_x + base + 4);
    float4 f0 = *(const float4*)(d_a + base), f1 = *(const float4*)(d_a + base + 4);
    float v[8] = {x0.x + f0.x, x0.y + f0.y, x0.z + f0.z, x0.w + f0.w,
                  x1.x + f1.x, x1.y + f1.y, x1.z + f1.z, x1.w + f1.w};
    float sum = 0.f, sq = 0.f;
    #pragma unroll
    for (int i = 0; i < 8; i++) { sum += v[i]; sq += v[i] * v[i]; }
    #pragma unroll
    for (int mask = 16; mask >= 1; mask >>= 1) {
        sum += __shfl_xor_sync(0xffffffffu, sum, mask);
        sq  += __shfl_xor_sync(0xffffffffu, sq, mask);
    }
    float mean = sum * (1.f / EE);
    float var = sq * (1.f / EE) - mean * mean;
    float inv = rsqrtf(var + 1e-5f);
    float4 g0 = *(const float4*)(gam + lane * 8), g1v = *(const float4*)(gam + lane * 8 + 4);
    float4 b0 = *(const float4*)(bet + lane * 8), b1v = *(const float4*)(bet + lane * 8 + 4);
    float gv[8] = {g0.x, g0.y, g0.z, g0.w, g1v.x, g1v.y, g1v.z, g1v.w};
    float bv[8] = {b0.x, b0.y, b0.z, b0.w, b1v.x, b1v.y, b1v.z, b1v.w};
    #pragma unroll
    for (int i = 0; i < 8; i++) v[i] = (v[i] - mean) * inv * gv[i] + bv[i];
    *(float4*)(d_x + base)     = make_float4(v[0], v[1], v[2], v[3]);
    *(float4*)(d_x + base + 4) = make_float4(v[4], v[5], v[6], v[7]);
    if (phi) {
        float out[8];
        qmap8(v, phi, out);
        store_q8(d_qh + base, out);
    }
}

// ---------------- 4. fused FFN on tensor cores (fp16 mma, fp32 accum) ----------------
#define HSP 40    // hs row stride (halves)
#define WSP 264   // ws row stride (halves)
__global__ __launch_bounds__(256, 2) void ffn_kernel(const float* __restrict__ theta,
                                                     const float* __restrict__ W1,
                                                     const float* __restrict__ b1,
                                                     int layer,
                                                     const float* __restrict__ b2) {
    __shared__ float qm[64][9];
    __shared__ float w1s[8][33];
    __shared__ __half hs[64][HSP];
    __shared__ __half ws[32][WSP];
    __shared__ float b1s[FF];
    __shared__ float b2s[256];
    const __half* __restrict__ W2h = d_w2h + (size_t)layer * FF * EE;
    const int t = threadIdx.x, w = t >> 5, lane = t & 31;
    const int qt = lane >> 2, tq = lane & 3;
    const int l7 = lane & 7, l3 = lane >> 3;
    const int wm = w >> 2, wn = w & 3;
    const int rowBase = blockIdx.x * 64;
    const unsigned hs_s = (unsigned)__cvta_generic_to_shared(hs);
    const unsigned ws_s = (unsigned)__cvta_generic_to_shared(ws);

    b2s[t] = b2[t];
    #pragma unroll
    for (int p = 0; p < 4; p++) b1s[t + p * 256] = b1[t + p * 256];
    #pragma unroll
    for (int i = 0; i < 2; i++) {
        int idx = t * 2 + i;
        int r = idx >> 3, j = idx & 7;
        qm[r][j] = cosf(d_x[(size_t)(rowBase + r) * EE + j]) * cosf(theta[j]);
    }

    float c[2][8][4];
    #pragma unroll
    for (int mt = 0; mt < 2; mt++)
        #pragma unroll
        for (int nt = 0; nt < 8; nt++)
            c[mt][nt][0] = c[mt][nt][1] = c[mt][nt][2] = c[mt][nt][3] = 0.f;

    for (int kt = 0; kt < FF / 32; kt++) {
        int k0g = kt * 32;
        __syncthreads();
        w1s[t >> 5][t & 31] = W1[(t >> 5) * FF + k0g + (t & 31)];
        {
            const uint4* w4 = (const uint4*)(W2h + (size_t)k0g * EE);
            #pragma unroll
            for (int p = 0; p < 4; p++) {
                int idx = p * 256 + t;
                *(uint4*)(&ws[idx >> 5][(idx & 31) * 8]) = w4[idx];
            }
        }
        __syncthreads();
        {
            int r = t & 63, cg = (t >> 6) * 8;
            #pragma unroll
            for (int i = 0; i < 8; i++) {
                int cc = cg + i;
                float h = b1s[k0g + cc];
                #pragma unroll
                for (int j = 0; j < 8; j++) h += qm[r][j] * w1s[j][cc];
                hs[r][cc] = __float2half(fmaxf(h, 0.f));
            }
        }
        __syncthreads();
        #pragma unroll
        for (int ks = 0; ks < 2; ks++) {
            unsigned a[2][4];
            #pragma unroll
            for (int mt = 0; mt < 2; mt++) {
                int mrow = wm * 32 + mt * 16;
                unsigned addr = hs_s + 2u * (unsigned)((mrow + l7 + 8 * (l3 & 1)) * HSP +
                                                       ks * 16 + 8 * (l3 >> 1));
                ldsm4(a[mt][0], a[mt][1], a[mt][2], a[mt][3], addr);
            }
            #pragma unroll
            for (int ng = 0; ng < 4; ng++) {
                int n0 = wn * 64 + ng * 16;
                unsigned baddr = ws_s + 2u * (unsigned)((ks * 16 + l7 + 8 * (l3 & 1)) * WSP +
                                                        n0 + 8 * (l3 >> 1));
                unsigned b0, b1r, b2r, b3;
                ldsm4t(b0, b1r, b2r, b3, baddr);
                MMA_F16(c[0][2*ng],   a[0][0], a[0][1], a[0][2], a[0][3], b0, b1r);
                MMA_F16(c[0][2*ng+1], a[0][0], a[0][1], a[0][2], a[0][3], b2r, b3);
                MMA_F16(c[1][2*ng],   a[1][0], a[1][1], a[1][2], a[1][3], b0, b1r);
                MMA_F16(c[1][2*ng+1], a[1][0], a[1][1], a[1][2], a[1][3], b2r, b3);
            }
        }
    }
    #pragma unroll
    for (int mt = 0; mt < 2; mt++) {
        int gr = rowBase + wm * 32 + mt * 16;
        #pragma unroll
        for (int nt = 0; nt < 8; nt++) {
            int col = wn * 64 + nt * 8 + 2 * tq;
            float bb0 = b2s[col], bb1 = b2s[col + 1];
            *(float2*)(d_a + (size_t)(gr + qt) * EE + col) =
                make_float2(c[mt][nt][0] + bb0, c[mt][nt][1] + bb1);
            *(float2*)(d_a + (size_t)(gr + qt + 8) * EE + col) =
                make_float2(c[mt][nt][2] + bb0, c[mt][nt][3] + bb1);
        }
    }
}

// ---------------- 5. mean over S + classifier head ----------------
__global__ void head_kernel(const float* __restrict__ Wc, const float* __restrict__ bc,
                            float* __restrict__ out) {
    __shared__ float sm[1024];
    __shared__ float mean[EE];
    int b = blockIdx.x;
    int e = threadIdx.x & 255;
    int chunk = threadIdx.x >> 8;
    float s = 0.f;
    for (int i = 0; i < SS / 4; i++) {
        int srow = chunk * (SS / 4) + i;
        s += d_x[((size_t)b * SS + srow) * EE + e];
    }
    sm[threadIdx.x] = s;
    __syncthreads();
    if (threadIdx.x < 256) {
        float tot = sm[e] + sm[e + 256] + sm[e + 512] + sm[e + 768];
        mean[e] = tot * (1.f / SS);
    }
    __syncthreads();
    if (threadIdx.x < NC) {
        float acc = bc[threadIdx.x];
        for (int ee = 0; ee < EE; ee++)
            acc += mean[ee] * Wc[ee * NC + threadIdx.x];
        out[b * NC + threadIdx.x] = acc;
    }
}

// ---------------- launch ----------------
extern "C" void kernel_launch(void* const* d_in, const int* in_sizes, int n_in,
                              void* d_out, int out_size) {
    const int*   tok   = (const int*)d_in[0];
    const float* emb   = (const float*)d_in[1];
    const float* phi   = (const float*)d_in[2];
    const float* theta = (const float*)d_in[3];
    const float* W1    = (const float*)d_in[4];
    const float* b1    = (const float*)d_in[5];
    const float* W2    = (const float*)d_in[6];
    const float* b2    = (const float*)d_in[7];
    const float* g1    = (const float*)d_in[8];
    const float* be1   = (const float*)d_in[9];
    const float* g2    = (const float*)d_in[10];
    const float* be2   = (const float*)d_in[11];
    const float* Wc    = (const float*)d_in[12];
    const float* bc    = (const float*)d_in[13];
    float* out = (float*)d_out;

    cudaFuncSetAttribute(attn_kernel, cudaFuncAttributeMaxDynamicSharedMemorySize, ATT_SMEM);

    w2cvt_kernel<<<LL * FF * EE / 4 / 256, 256>>>(W2);
    embed_q_kernel<<<ROWS * 32 / 256, 256>>>(tok, emb, phi);
    for (int l = 0; l < LL; l++) {
        attn_kernel<<<dim3(SS / 64, BB), 256, ATT_SMEM>>>(g1 + l * EE, be1 + l * EE);
        ffn_kernel<<<ROWS / 64, 256>>>(theta + l * NQ, W1 + (size_t)l * NQ * FF,
                                       b1 + l * FF, l, b2 + l * EE);
        addln_kernel<<<ROWS / 8, 256>>>(g2 + l * EE, be2 + l * EE,
                                        (l < LL - 1) ? (phi + (l + 1) * NQ) : nullptr);
    }
    head_kernel<<<BB, 1024>>>(Wc, bc, out);
}